// round 4
// baseline (speedup 1.0000x reference)
#include <cuda_runtime.h>
#include <cuda_bf16.h>
#include <cstdint>

#define BATCH 8
#define NPTS  4096
#define MROWS 32768
#define FD    512

// GEMM tiling
#define BM 128
#define BN 128
#define BK 32
#define LDA 40                    // halves per smem row (pad 8)
#define ARR_BYTES (BM * LDA * 2)  // 10240
#define STAGE_BYTES (4 * ARR_BYTES)
#define SMEM_TOTAL (2 * STAGE_BYTES)   // 81920

// ---------------------------------------------------------------------------
// Device scratch
// ---------------------------------------------------------------------------
__device__ float          g_feat[MROWS * 12];
__device__ __nv_bfloat16  g_lat_hi[MROWS * FD];
__device__ __nv_bfloat16  g_lat_lo[MROWS * FD];
__device__ __nv_bfloat16  g_h_hi[MROWS * FD];
__device__ __nv_bfloat16  g_h_lo[MROWS * FD];
__device__ float          g_std1[MROWS];
__device__ float          g_std2[MROWS];
__device__ __nv_bfloat16  g_w1T_hi[FD * FD];
__device__ __nv_bfloat16  g_w1T_lo[FD * FD];
__device__ __nv_bfloat16  g_wrT_hi[FD * FD];
__device__ __nv_bfloat16  g_wrT_lo[FD * FD];

// ---------------------------------------------------------------------------
// Helpers
// ---------------------------------------------------------------------------
__device__ __forceinline__ uint32_t smem_u32(const void* p) {
    uint32_t a;
    asm("{ .reg .u64 t; cvta.to.shared.u64 t, %1; cvt.u32.u64 %0, t; }" : "=r"(a) : "l"(p));
    return a;
}

__device__ __forceinline__ void cp16(uint32_t s, const void* g) {
    asm volatile("cp.async.cg.shared.global [%0], [%1], 16;" :: "r"(s), "l"(g));
}
__device__ __forceinline__ void cp_commit() { asm volatile("cp.async.commit_group;"); }
template <int N>
__device__ __forceinline__ void cp_wait() { asm volatile("cp.async.wait_group %0;" :: "n"(N)); }

__device__ __forceinline__ void ldmx4(uint32_t addr, uint32_t& r0, uint32_t& r1, uint32_t& r2, uint32_t& r3) {
    asm volatile("ldmatrix.sync.aligned.m8n8.x4.shared.b16 {%0,%1,%2,%3}, [%4];"
        : "=r"(r0), "=r"(r1), "=r"(r2), "=r"(r3) : "r"(addr));
}

__device__ __forceinline__ void mma_bf16(float* c, const uint32_t* a, const uint32_t* b) {
    asm volatile(
        "mma.sync.aligned.m16n8k16.row.col.f32.bf16.bf16.f32 "
        "{%0,%1,%2,%3}, {%4,%5,%6,%7}, {%8,%9}, {%0,%1,%2,%3};"
        : "+f"(c[0]), "+f"(c[1]), "+f"(c[2]), "+f"(c[3])
        : "r"(a[0]), "r"(a[1]), "r"(a[2]), "r"(a[3]), "r"(b[0]), "r"(b[1]));
}

__device__ __forceinline__ void split2(float x, __nv_bfloat16& h, __nv_bfloat16& l) {
    h = __float2bfloat16(x);
    l = __float2bfloat16(x - __bfloat162float(h));
}

// ---------------------------------------------------------------------------
// kNN + local covariance
// ---------------------------------------------------------------------------
__global__ __launch_bounds__(256) void knn_feat_kernel(
    const float* __restrict__ rp, float* __restrict__ feat)
{
    __shared__ float px[NPTS], py[NPTS], pz[NPTS];
    const int b = blockIdx.y;
    const float* base = rp + b * 3 * NPTS;
    for (int i = threadIdx.x; i < NPTS; i += 256) {
        px[i] = base[i]; py[i] = base[NPTS + i]; pz[i] = base[2 * NPTS + i];
    }
    __syncthreads();

    const int n = blockIdx.x * 256 + threadIdx.x;
    const float xi = px[n], yi = py[n], zi = pz[n];
    const float xxi = xi * xi + yi * yi + zi * zi;

    float bestv = -1e30f; int bestj = 0;
    for (int j = 0; j < NPTS; j++) {
        const float xj = px[j], yj = py[j], zj = pz[j];
        const float d = 2.0f * (xi * xj + yi * yj + zi * zj) - xxi - (xj * xj + yj * yj + zj * zj);
        if (j != n && d > bestv) { bestv = d; bestj = j; }
    }
    const float nx = px[bestj], ny = py[bestj], nz = pz[bestj];
    float* f = feat + (size_t)(b * NPTS + n) * 12;
    f[0] = xi;      f[1] = yi;      f[2] = zi;
    f[3] = xi * nx; f[4] = xi * ny; f[5] = xi * nz;
    f[6] = yi * nx; f[7] = yi * ny; f[8] = yi * nz;
    f[9] = zi * nx; f[10] = zi * ny; f[11] = zi * nz;
}

// ---------------------------------------------------------------------------
// fp32 -> bf16 hi/lo split (bulk)
// ---------------------------------------------------------------------------
__global__ __launch_bounds__(256) void conv_split_kernel(
    const float* __restrict__ x, __nv_bfloat16* __restrict__ hi,
    __nv_bfloat16* __restrict__ lo, int n4)
{
    for (int i = blockIdx.x * 256 + threadIdx.x; i < n4; i += gridDim.x * 256) {
        float4 v = ((const float4*)x)[i];
        __nv_bfloat16 h0,h1,h2,h3,l0,l1,l2,l3;
        split2(v.x,h0,l0); split2(v.y,h1,l1); split2(v.z,h2,l2); split2(v.w,h3,l3);
        __nv_bfloat162* ph = (__nv_bfloat162*)hi + i * 2;
        __nv_bfloat162* pl = (__nv_bfloat162*)lo + i * 2;
        ph[0] = __nv_bfloat162(h0, h1); ph[1] = __nv_bfloat162(h2, h3);
        pl[0] = __nv_bfloat162(l0, l1); pl[1] = __nv_bfloat162(l2, l3);
    }
}

// ---------------------------------------------------------------------------
// W[512,512] (k-major) -> WT[n][k] bf16 hi/lo
// ---------------------------------------------------------------------------
__global__ __launch_bounds__(256) void transW_kernel(
    const float* __restrict__ W, __nv_bfloat16* __restrict__ th, __nv_bfloat16* __restrict__ tl)
{
    __shared__ float t[32][33];
    const int n0 = blockIdx.x * 32, k0 = blockIdx.y * 32;
    const int tx = threadIdx.x & 31, ty = threadIdx.x >> 5;
    #pragma unroll
    for (int i = 0; i < 4; i++)
        t[ty + i * 8][tx] = W[(size_t)(k0 + ty + i * 8) * FD + n0 + tx];
    __syncthreads();
    #pragma unroll
    for (int i = 0; i < 4; i++) {
        float v = t[tx][ty + i * 8];
        __nv_bfloat16 h, l; split2(v, h, l);
        size_t o = (size_t)(n0 + ty + i * 8) * FD + k0 + tx;
        th[o] = h; tl[o] = l;
    }
}

// ---------------------------------------------------------------------------
// out[row] = (prev ? prev[row] : 0) + b2[0]   (pre-init for fused dot atomics)
// ---------------------------------------------------------------------------
__global__ __launch_bounds__(256) void init_out_kernel(
    const float* __restrict__ prev, const float* __restrict__ b2, float* __restrict__ out)
{
    const int i = blockIdx.x * 256 + threadIdx.x;
    out[i] = (prev ? prev[i] : 0.0f) + b2[0];
}

// ---------------------------------------------------------------------------
// Split-bf16 mma.sync GEMM.
//  Mode 1 (dotOut == nullptr):  H = relu(A@B^T + A2@Wtail + bias) -> outHi/outLo
//  Mode 2 (dotOut != nullptr):  v = relu(A@B^T + A + bias); atomicAdd(dotOut, v@w2)
// ---------------------------------------------------------------------------
__global__ __launch_bounds__(256, 2) void gemm_mma_kernel(
    const __nv_bfloat16* __restrict__ Ahi, const __nv_bfloat16* __restrict__ Alo,
    const __nv_bfloat16* __restrict__ Bhi, const __nv_bfloat16* __restrict__ Blo,
    const float* __restrict__ bias,
    const float* __restrict__ A2, const int K2, const float* __restrict__ Wtail,
    __nv_bfloat16* __restrict__ outHi, __nv_bfloat16* __restrict__ outLo,
    const float* __restrict__ w2, float* __restrict__ dotOut)
{
    extern __shared__ __align__(16) char dsm[];
    const uint32_t sbase = smem_u32(dsm);

    const int tid = threadIdx.x;
    const int m0 = blockIdx.y * BM;
    const int n0 = blockIdx.x * BN;
    const int warp = tid >> 5, lane = tid & 31;
    const int warp_m = warp >> 2;          // 0..1 -> 64 rows
    const int warp_n = warp & 3;           // 0..3 -> 32 cols

    // loader indices
    const int lr0 = tid >> 2;              // 0..63  (also +64)
    const int lkq = tid & 3;

    const size_t gA0 = (size_t)(m0 + lr0) * FD + lkq * 8;
    const size_t gA1 = (size_t)(m0 + lr0 + 64) * FD + lkq * 8;
    const size_t gB0 = (size_t)(n0 + lr0) * FD + lkq * 8;
    const size_t gB1 = (size_t)(n0 + lr0 + 64) * FD + lkq * 8;
    const uint32_t so0 = (uint32_t)(lr0 * LDA * 2 + lkq * 16);
    const uint32_t so1 = (uint32_t)((lr0 + 64) * LDA * 2 + lkq * 16);

    auto issue = [&](int chunk, uint32_t stoff) {
        const int kc = chunk * BK;
        const uint32_t st = sbase + stoff;
        cp16(st + 0 * ARR_BYTES + so0, Ahi + gA0 + kc);
        cp16(st + 0 * ARR_BYTES + so1, Ahi + gA1 + kc);
        cp16(st + 1 * ARR_BYTES + so0, Alo + gA0 + kc);
        cp16(st + 1 * ARR_BYTES + so1, Alo + gA1 + kc);
        cp16(st + 2 * ARR_BYTES + so0, Bhi + gB0 + kc);
        cp16(st + 2 * ARR_BYTES + so1, Bhi + gB1 + kc);
        cp16(st + 3 * ARR_BYTES + so0, Blo + gB0 + kc);
        cp16(st + 3 * ARR_BYTES + so1, Blo + gB1 + kc);
        cp_commit();
    };

    float c[4][4][4];
    #pragma unroll
    for (int i = 0; i < 4; i++)
        #pragma unroll
        for (int j = 0; j < 4; j++)
            #pragma unroll
            for (int q = 0; q < 4; q++) c[i][j][q] = 0.0f;

    const int arow = (lane & 15);
    const uint32_t acolb = (uint32_t)((lane >> 4) * 16);

    // precomputed smem row addresses (array/stage offsets fold to immediates)
    uint32_t rA[4], rB[2];
    #pragma unroll
    for (int mt = 0; mt < 4; mt++)
        rA[mt] = sbase + (uint32_t)((warp_m * 64 + mt * 16 + arow) * (LDA * 2)) + acolb;
    #pragma unroll
    for (int pr = 0; pr < 2; pr++)
        rB[pr] = sbase + (uint32_t)((warp_n * 32 + pr * 16 + arow) * (LDA * 2)) + acolb;

    auto compute = [&](uint32_t stoff) {
        #pragma unroll
        for (int kk = 0; kk < 2; kk++) {
            const uint32_t kb = stoff + (uint32_t)(kk * 32);
            uint32_t ah[4][4], al[4][4], bh[4][2], bl[4][2];
            #pragma unroll
            for (int mt = 0; mt < 4; mt++) {
                ldmx4(rA[mt] + kb + 0 * ARR_BYTES, ah[mt][0], ah[mt][1], ah[mt][2], ah[mt][3]);
                ldmx4(rA[mt] + kb + 1 * ARR_BYTES, al[mt][0], al[mt][1], al[mt][2], al[mt][3]);
            }
            #pragma unroll
            for (int pr = 0; pr < 2; pr++) {
                uint32_t r0, r1, r2, r3;
                ldmx4(rB[pr] + kb + 2 * ARR_BYTES, r0, r1, r2, r3);
                bh[2*pr][0] = r0; bh[2*pr][1] = r2; bh[2*pr+1][0] = r1; bh[2*pr+1][1] = r3;
                ldmx4(rB[pr] + kb + 3 * ARR_BYTES, r0, r1, r2, r3);
                bl[2*pr][0] = r0; bl[2*pr][1] = r2; bl[2*pr+1][0] = r1; bl[2*pr+1][1] = r3;
            }
            #pragma unroll
            for (int mt = 0; mt < 4; mt++)
                #pragma unroll
                for (int nt = 0; nt < 4; nt++) {
                    mma_bf16(c[mt][nt], ah[mt], bh[nt]);
                    mma_bf16(c[mt][nt], al[mt], bh[nt]);
                    mma_bf16(c[mt][nt], ah[mt], bl[nt]);
                }
        }
    };

    issue(0, 0);

    #pragma unroll 1
    for (int cc = 0; cc < 8; cc++) {
        // even chunk: compute stage0, prefetch stage1
        cp_wait<0>(); __syncthreads();
        issue(2 * cc + 1, STAGE_BYTES);
        compute(0);
        // odd chunk: compute stage1, prefetch stage0
        cp_wait<0>(); __syncthreads();
        if (cc < 7) issue(2 * cc + 2, 0);
        compute(STAGE_BYTES);
    }

    // ---- epilogue ----
    const int qrow = lane >> 2;            // 0..7
    const int qcol = (lane & 3) * 2;       // 0,2,4,6

    if (dotOut == nullptr) {
        // GEMM1 path: K2 tail + bias + relu, store hi/lo bf16
        #pragma unroll
        for (int mt = 0; mt < 4; mt++) {
            const int rowA = m0 + warp_m * 64 + mt * 16 + qrow;
            const int rowB = rowA + 8;

            float a2A[12], a2B[12];
            for (int k = 0; k < K2; k++) {
                a2A[k] = __ldg(A2 + (size_t)rowA * K2 + k);
                a2B[k] = __ldg(A2 + (size_t)rowB * K2 + k);
            }

            #pragma unroll
            for (int nt = 0; nt < 4; nt++) {
                const int colg = n0 + warp_n * 32 + nt * 8 + qcol;
                const float b0 = __ldg(bias + colg), b1 = __ldg(bias + colg + 1);
                float v0 = c[mt][nt][0] + b0, v1 = c[mt][nt][1] + b1;
                float v2 = c[mt][nt][2] + b0, v3 = c[mt][nt][3] + b1;

                for (int k = 0; k < K2; k++) {
                    const float w0 = __ldg(Wtail + (size_t)k * FD + colg);
                    const float w1 = __ldg(Wtail + (size_t)k * FD + colg + 1);
                    v0 += a2A[k] * w0; v1 += a2A[k] * w1;
                    v2 += a2B[k] * w0; v3 += a2B[k] * w1;
                }
                v0 = fmaxf(v0, 0.0f); v1 = fmaxf(v1, 0.0f);
                v2 = fmaxf(v2, 0.0f); v3 = fmaxf(v3, 0.0f);

                __nv_bfloat16 h0,h1,h2,h3,l0,l1,l2,l3;
                split2(v0,h0,l0); split2(v1,h1,l1);
                split2(v2,h2,l2); split2(v3,h3,l3);
                *(__nv_bfloat162*)(outHi + (size_t)rowA * FD + colg) = __nv_bfloat162(h0, h1);
                *(__nv_bfloat162*)(outLo + (size_t)rowA * FD + colg) = __nv_bfloat162(l0, l1);
                *(__nv_bfloat162*)(outHi + (size_t)rowB * FD + colg) = __nv_bfloat162(h2, h3);
                *(__nv_bfloat162*)(outLo + (size_t)rowB * FD + colg) = __nv_bfloat162(l2, l3);
            }
        }
    } else {
        // GEMM2 path: residual(A) + bias + relu, fused dot with w2 -> atomicAdd
        #pragma unroll
        for (int mt = 0; mt < 4; mt++) {
            const int rowA = m0 + warp_m * 64 + mt * 16 + qrow;
            const int rowB = rowA + 8;
            float sA = 0.0f, sB = 0.0f;

            #pragma unroll
            for (int nt = 0; nt < 4; nt++) {
                const int colg = n0 + warp_n * 32 + nt * 8 + qcol;
                const float b0 = __ldg(bias + colg), b1 = __ldg(bias + colg + 1);
                float v0 = c[mt][nt][0] + b0, v1 = c[mt][nt][1] + b1;
                float v2 = c[mt][nt][2] + b0, v3 = c[mt][nt][3] + b1;

                float2 hA = __bfloat1622float2(*(const __nv_bfloat162*)(Ahi + (size_t)rowA * FD + colg));
                float2 lA = __bfloat1622float2(*(const __nv_bfloat162*)(Alo + (size_t)rowA * FD + colg));
                float2 hB = __bfloat1622float2(*(const __nv_bfloat162*)(Ahi + (size_t)rowB * FD + colg));
                float2 lB = __bfloat1622float2(*(const __nv_bfloat162*)(Alo + (size_t)rowB * FD + colg));
                v0 += hA.x + lA.x; v1 += hA.y + lA.y;
                v2 += hB.x + lB.x; v3 += hB.y + lB.y;

                v0 = fmaxf(v0, 0.0f); v1 = fmaxf(v1, 0.0f);
                v2 = fmaxf(v2, 0.0f); v3 = fmaxf(v3, 0.0f);

                const float w0 = __ldg(w2 + colg), w1 = __ldg(w2 + colg + 1);
                sA += v0 * w0 + v1 * w1;
                sB += v2 * w0 + v3 * w1;
            }
            // reduce over the 4 lanes sharing this row (lane bits 0..1)
            sA += __shfl_xor_sync(0xFFFFFFFFu, sA, 1);
            sA += __shfl_xor_sync(0xFFFFFFFFu, sA, 2);
            sB += __shfl_xor_sync(0xFFFFFFFFu, sB, 1);
            sB += __shfl_xor_sync(0xFFFFFFFFu, sB, 2);
            if ((lane & 3) == 0) {
                atomicAdd(dotOut + rowA, sA);
                atomicAdd(dotOut + rowB, sB);
            }
        }
    }
}

// ---------------------------------------------------------------------------
// Host orchestration
// ---------------------------------------------------------------------------
extern "C" void kernel_launch(void* const* d_in, const int* in_sizes, int n_in,
                              void* d_out, int out_size)
{
    const float* latent = (const float*)d_in[0];
    const float* rp     = (const float*)d_in[1];
    const float* w1[3] = {(const float*)d_in[2],  (const float*)d_in[8],  (const float*)d_in[14]};
    const float* b1[3] = {(const float*)d_in[3],  (const float*)d_in[9],  (const float*)d_in[15]};
    const float* wr[3] = {(const float*)d_in[4],  (const float*)d_in[10], (const float*)d_in[16]};
    const float* br[3] = {(const float*)d_in[5],  (const float*)d_in[11], (const float*)d_in[17]};
    const float* w2[3] = {(const float*)d_in[6],  (const float*)d_in[12], (const float*)d_in[18]};
    const float* b2[3] = {(const float*)d_in[7],  (const float*)d_in[13], (const float*)d_in[19]};

    float *feat, *std1, *std2;
    __nv_bfloat16 *lat_hi, *lat_lo, *h_hi, *h_lo, *w1T_hi, *w1T_lo, *wrT_hi, *wrT_lo;
    cudaGetSymbolAddress((void**)&feat,   g_feat);
    cudaGetSymbolAddress((void**)&lat_hi, g_lat_hi);
    cudaGetSymbolAddress((void**)&lat_lo, g_lat_lo);
    cudaGetSymbolAddress((void**)&h_hi,   g_h_hi);
    cudaGetSymbolAddress((void**)&h_lo,   g_h_lo);
    cudaGetSymbolAddress((void**)&std1,   g_std1);
    cudaGetSymbolAddress((void**)&std2,   g_std2);
    cudaGetSymbolAddress((void**)&w1T_hi, g_w1T_hi);
    cudaGetSymbolAddress((void**)&w1T_lo, g_w1T_lo);
    cudaGetSymbolAddress((void**)&wrT_hi, g_wrT_hi);
    cudaGetSymbolAddress((void**)&wrT_lo, g_wrT_lo);

    float* out = (float*)d_out;

    cudaFuncSetAttribute(gemm_mma_kernel, cudaFuncAttributeMaxDynamicSharedMemorySize, SMEM_TOTAL);

    const dim3 ggrid(FD / BN, MROWS / BM);   // (4, 256)
    const dim3 tgrid(16, 16);

    conv_split_kernel<<<2048, 256>>>(latent, lat_hi, lat_lo, MROWS * FD / 4);
    knn_feat_kernel<<<dim3(NPTS / 256, BATCH), 256>>>(rp, feat);

    const float* stdprev[3] = {nullptr, std1, std2};
    const float* a2s[3]     = {feat, std1, std2};
    const int    k2s[3]     = {12, 1, 1};
    float*       stdout_[3] = {std1, std2, out};

    for (int s = 0; s < 3; s++) {
        transW_kernel<<<tgrid, 256>>>(w1[s], w1T_hi, w1T_lo);
        gemm_mma_kernel<<<ggrid, 256, SMEM_TOTAL>>>(
            lat_hi, lat_lo, w1T_hi, w1T_lo, b1[s],
            a2s[s], k2s[s], w1[s] + (size_t)FD * FD,
            h_hi, h_lo, nullptr, nullptr);
        transW_kernel<<<tgrid, 256>>>(wr[s], wrT_hi, wrT_lo);
        init_out_kernel<<<MROWS / 256, 256>>>(stdprev[s], b2[s], stdout_[s]);
        gemm_mma_kernel<<<ggrid, 256, SMEM_TOTAL>>>(
            h_hi, h_lo, wrT_hi, wrT_lo, br[s],
            nullptr, 0, nullptr,
            nullptr, nullptr, w2[s], stdout_[s]);
    }
}

// round 5
// speedup vs baseline: 1.4951x; 1.4951x over previous
#include <cuda_runtime.h>
#include <cuda_bf16.h>
#include <cstdint>

#define BATCH 8
#define NPTS  4096
#define MROWS 32768
#define FD    512

// GEMM tiling
#define BM 128
#define BN 128
#define BK 32
#define LDA 40                    // halves per smem row (pad 8)
#define ARR_BYTES (BM * LDA * 2)  // 10240
#define STAGE_BYTES (4 * ARR_BYTES)
#define SMEM_TOTAL (2 * STAGE_BYTES)   // 81920

// ---------------------------------------------------------------------------
// Device scratch
// ---------------------------------------------------------------------------
__device__ float          g_feat[MROWS * 12];
__device__ __nv_bfloat16  g_lat_hi[MROWS * FD];
__device__ __nv_bfloat16  g_lat_lo[MROWS * FD];
__device__ __nv_bfloat16  g_h_hi[MROWS * FD];
__device__ __nv_bfloat16  g_h_lo[MROWS * FD];
__device__ float          g_std1[MROWS];
__device__ float          g_std2[MROWS];
__device__ __nv_bfloat16  g_w1T_hi[FD * FD];
__device__ __nv_bfloat16  g_w1T_lo[FD * FD];
__device__ __nv_bfloat16  g_wrT_hi[FD * FD];
__device__ __nv_bfloat16  g_wrT_lo[FD * FD];

// ---------------------------------------------------------------------------
// Helpers
// ---------------------------------------------------------------------------
__device__ __forceinline__ uint32_t smem_u32(const void* p) {
    uint32_t a;
    asm("{ .reg .u64 t; cvta.to.shared.u64 t, %1; cvt.u32.u64 %0, t; }" : "=r"(a) : "l"(p));
    return a;
}

__device__ __forceinline__ void cp16(uint32_t s, const void* g) {
    asm volatile("cp.async.cg.shared.global [%0], [%1], 16;" :: "r"(s), "l"(g));
}
__device__ __forceinline__ void cp_commit() { asm volatile("cp.async.commit_group;"); }
template <int N>
__device__ __forceinline__ void cp_wait() { asm volatile("cp.async.wait_group %0;" :: "n"(N)); }

__device__ __forceinline__ void ldmx4(uint32_t addr, uint32_t& r0, uint32_t& r1, uint32_t& r2, uint32_t& r3) {
    asm volatile("ldmatrix.sync.aligned.m8n8.x4.shared.b16 {%0,%1,%2,%3}, [%4];"
        : "=r"(r0), "=r"(r1), "=r"(r2), "=r"(r3) : "r"(addr));
}

__device__ __forceinline__ void mma_bf16(float* c, const uint32_t* a, const uint32_t* b) {
    asm volatile(
        "mma.sync.aligned.m16n8k16.row.col.f32.bf16.bf16.f32 "
        "{%0,%1,%2,%3}, {%4,%5,%6,%7}, {%8,%9}, {%0,%1,%2,%3};"
        : "+f"(c[0]), "+f"(c[1]), "+f"(c[2]), "+f"(c[3])
        : "r"(a[0]), "r"(a[1]), "r"(a[2]), "r"(a[3]), "r"(b[0]), "r"(b[1]));
}

__device__ __forceinline__ void split2(float x, __nv_bfloat16& h, __nv_bfloat16& l) {
    h = __float2bfloat16(x);
    l = __float2bfloat16(x - __bfloat162float(h));
}

// ---------------------------------------------------------------------------
// kNN + local covariance
// ---------------------------------------------------------------------------
__global__ __launch_bounds__(256) void knn_feat_kernel(
    const float* __restrict__ rp, float* __restrict__ feat)
{
    __shared__ float px[NPTS], py[NPTS], pz[NPTS];
    const int b = blockIdx.y;
    const float* base = rp + b * 3 * NPTS;
    for (int i = threadIdx.x; i < NPTS; i += 256) {
        px[i] = base[i]; py[i] = base[NPTS + i]; pz[i] = base[2 * NPTS + i];
    }
    __syncthreads();

    const int n = blockIdx.x * 256 + threadIdx.x;
    const float xi = px[n], yi = py[n], zi = pz[n];
    const float xxi = xi * xi + yi * yi + zi * zi;

    float bestv = -1e30f; int bestj = 0;
    for (int j = 0; j < NPTS; j++) {
        const float xj = px[j], yj = py[j], zj = pz[j];
        const float d = 2.0f * (xi * xj + yi * yj + zi * zj) - xxi - (xj * xj + yj * yj + zj * zj);
        if (j != n && d > bestv) { bestv = d; bestj = j; }
    }
    const float nx = px[bestj], ny = py[bestj], nz = pz[bestj];
    float* f = feat + (size_t)(b * NPTS + n) * 12;
    f[0] = xi;      f[1] = yi;      f[2] = zi;
    f[3] = xi * nx; f[4] = xi * ny; f[5] = xi * nz;
    f[6] = yi * nx; f[7] = yi * ny; f[8] = yi * nz;
    f[9] = zi * nx; f[10] = zi * ny; f[11] = zi * nz;
}

// ---------------------------------------------------------------------------
// fp32 -> bf16 hi/lo split (bulk)
// ---------------------------------------------------------------------------
__global__ __launch_bounds__(256) void conv_split_kernel(
    const float* __restrict__ x, __nv_bfloat16* __restrict__ hi,
    __nv_bfloat16* __restrict__ lo, int n4)
{
    for (int i = blockIdx.x * 256 + threadIdx.x; i < n4; i += gridDim.x * 256) {
        float4 v = ((const float4*)x)[i];
        __nv_bfloat16 h0,h1,h2,h3,l0,l1,l2,l3;
        split2(v.x,h0,l0); split2(v.y,h1,l1); split2(v.z,h2,l2); split2(v.w,h3,l3);
        __nv_bfloat162* ph = (__nv_bfloat162*)hi + i * 2;
        __nv_bfloat162* pl = (__nv_bfloat162*)lo + i * 2;
        ph[0] = __nv_bfloat162(h0, h1); ph[1] = __nv_bfloat162(h2, h3);
        pl[0] = __nv_bfloat162(l0, l1); pl[1] = __nv_bfloat162(l2, l3);
    }
}

// ---------------------------------------------------------------------------
// W[512,512] (k-major) -> WT[n][k] bf16 hi/lo
// ---------------------------------------------------------------------------
__global__ __launch_bounds__(256) void transW_kernel(
    const float* __restrict__ W, __nv_bfloat16* __restrict__ th, __nv_bfloat16* __restrict__ tl)
{
    __shared__ float t[32][33];
    const int n0 = blockIdx.x * 32, k0 = blockIdx.y * 32;
    const int tx = threadIdx.x & 31, ty = threadIdx.x >> 5;
    #pragma unroll
    for (int i = 0; i < 4; i++)
        t[ty + i * 8][tx] = W[(size_t)(k0 + ty + i * 8) * FD + n0 + tx];
    __syncthreads();
    #pragma unroll
    for (int i = 0; i < 4; i++) {
        float v = t[tx][ty + i * 8];
        __nv_bfloat16 h, l; split2(v, h, l);
        size_t o = (size_t)(n0 + ty + i * 8) * FD + k0 + tx;
        th[o] = h; tl[o] = l;
    }
}

// ---------------------------------------------------------------------------
// out[row] = (prev ? prev[row] : 0) + b2[0]   (pre-init for fused dot atomics)
// ---------------------------------------------------------------------------
__global__ __launch_bounds__(256) void init_out_kernel(
    const float* __restrict__ prev, const float* __restrict__ b2, float* __restrict__ out)
{
    const int i = blockIdx.x * 256 + threadIdx.x;
    out[i] = (prev ? prev[i] : 0.0f) + b2[0];
}

// ---------------------------------------------------------------------------
// Split-bf16 mma.sync GEMM (R3-verified mainloop).
//  Mode 1 (dotOut == nullptr):  H = relu(A@B^T + A2@Wtail + bias) -> outHi/outLo
//  Mode 2 (dotOut != nullptr):  v = relu(A@B^T + A + bias); atomicAdd(dotOut, v@w2)
// ---------------------------------------------------------------------------
__global__ __launch_bounds__(256) void gemm_mma_kernel(
    const __nv_bfloat16* __restrict__ Ahi, const __nv_bfloat16* __restrict__ Alo,
    const __nv_bfloat16* __restrict__ Bhi, const __nv_bfloat16* __restrict__ Blo,
    const float* __restrict__ bias,
    const float* __restrict__ A2, const int K2, const float* __restrict__ Wtail,
    __nv_bfloat16* __restrict__ outHi, __nv_bfloat16* __restrict__ outLo,
    const float* __restrict__ w2, float* __restrict__ dotOut)
{
    extern __shared__ __align__(16) char dsm[];
    const uint32_t sbase = smem_u32(dsm);

    const int tid = threadIdx.x;
    const int m0 = blockIdx.y * BM;
    const int n0 = blockIdx.x * BN;
    const int warp = tid >> 5, lane = tid & 31;
    const int warp_m = warp >> 2;          // 0..1 -> 64 rows
    const int warp_n = warp & 3;           // 0..3 -> 32 cols

    // loader indices: id -> row = id>>2, kq = id&3 (16B each)
    const int lr0 = tid >> 2;              // 0..63  (also +64)
    const int lkq = tid & 3;

    const size_t gA0 = (size_t)(m0 + lr0) * FD + lkq * 8;
    const size_t gA1 = (size_t)(m0 + lr0 + 64) * FD + lkq * 8;
    const size_t gB0 = (size_t)(n0 + lr0) * FD + lkq * 8;
    const size_t gB1 = (size_t)(n0 + lr0 + 64) * FD + lkq * 8;
    const uint32_t so0 = (uint32_t)(lr0 * LDA * 2 + lkq * 16);
    const uint32_t so1 = (uint32_t)((lr0 + 64) * LDA * 2 + lkq * 16);

    auto issue = [&](int chunk) {
        const int kc = chunk * BK;
        const uint32_t st = sbase + (chunk & 1) * STAGE_BYTES;
        cp16(st + 0 * ARR_BYTES + so0, Ahi + gA0 + kc);
        cp16(st + 0 * ARR_BYTES + so1, Ahi + gA1 + kc);
        cp16(st + 1 * ARR_BYTES + so0, Alo + gA0 + kc);
        cp16(st + 1 * ARR_BYTES + so1, Alo + gA1 + kc);
        cp16(st + 2 * ARR_BYTES + so0, Bhi + gB0 + kc);
        cp16(st + 2 * ARR_BYTES + so1, Bhi + gB1 + kc);
        cp16(st + 3 * ARR_BYTES + so0, Blo + gB0 + kc);
        cp16(st + 3 * ARR_BYTES + so1, Blo + gB1 + kc);
        cp_commit();
    };

    float c[4][4][4];
    #pragma unroll
    for (int i = 0; i < 4; i++)
        #pragma unroll
        for (int j = 0; j < 4; j++)
            #pragma unroll
            for (int q = 0; q < 4; q++) c[i][j][q] = 0.0f;

    issue(0);

    const int arow = (lane & 15);
    const int acolb = (lane >> 4) * 16;

    #pragma unroll 1
    for (int ch = 0; ch < FD / BK; ch++) {
        if (ch + 1 < FD / BK) { issue(ch + 1); cp_wait<1>(); }
        else                  { cp_wait<0>(); }
        __syncthreads();

        const uint32_t st = sbase + (ch & 1) * STAGE_BYTES;
        const uint32_t sAh = st + 0 * ARR_BYTES;
        const uint32_t sAl = st + 1 * ARR_BYTES;
        const uint32_t sBh = st + 2 * ARR_BYTES;
        const uint32_t sBl = st + 3 * ARR_BYTES;

        #pragma unroll
        for (int kk = 0; kk < 2; kk++) {
            const uint32_t kb = kk * 32 + acolb;
            uint32_t ah[4][4], al[4][4], bh[4][2], bl[4][2];
            #pragma unroll
            for (int mt = 0; mt < 4; mt++) {
                const uint32_t ro = (uint32_t)((warp_m * 64 + mt * 16 + arow) * (LDA * 2)) + kb;
                ldmx4(sAh + ro, ah[mt][0], ah[mt][1], ah[mt][2], ah[mt][3]);
                ldmx4(sAl + ro, al[mt][0], al[mt][1], al[mt][2], al[mt][3]);
            }
            #pragma unroll
            for (int pr = 0; pr < 2; pr++) {
                const uint32_t ro = (uint32_t)((warp_n * 32 + pr * 16 + arow) * (LDA * 2)) + kb;
                uint32_t r0, r1, r2, r3;
                ldmx4(sBh + ro, r0, r1, r2, r3);
                bh[2*pr][0] = r0; bh[2*pr][1] = r2; bh[2*pr+1][0] = r1; bh[2*pr+1][1] = r3;
                ldmx4(sBl + ro, r0, r1, r2, r3);
                bl[2*pr][0] = r0; bl[2*pr][1] = r2; bl[2*pr+1][0] = r1; bl[2*pr+1][1] = r3;
            }
            #pragma unroll
            for (int mt = 0; mt < 4; mt++)
                #pragma unroll
                for (int nt = 0; nt < 4; nt++) {
                    mma_bf16(c[mt][nt], ah[mt], bh[nt]);
                    mma_bf16(c[mt][nt], al[mt], bh[nt]);
                    mma_bf16(c[mt][nt], ah[mt], bl[nt]);
                }
        }
        __syncthreads();
    }

    // ---- epilogue ----
    const int qrow = lane >> 2;            // 0..7
    const int qcol = (lane & 3) * 2;       // 0,2,4,6

    if (dotOut == nullptr) {
        // GEMM1 path: K2 tail + bias + relu, store hi/lo bf16
        #pragma unroll
        for (int mt = 0; mt < 4; mt++) {
            const int rowA = m0 + warp_m * 64 + mt * 16 + qrow;
            const int rowB = rowA + 8;

            float a2A[12], a2B[12];
            for (int k = 0; k < K2; k++) {
                a2A[k] = __ldg(A2 + (size_t)rowA * K2 + k);
                a2B[k] = __ldg(A2 + (size_t)rowB * K2 + k);
            }

            #pragma unroll
            for (int nt = 0; nt < 4; nt++) {
                const int colg = n0 + warp_n * 32 + nt * 8 + qcol;
                const float b0 = __ldg(bias + colg), b1 = __ldg(bias + colg + 1);
                float v0 = c[mt][nt][0] + b0, v1 = c[mt][nt][1] + b1;
                float v2 = c[mt][nt][2] + b0, v3 = c[mt][nt][3] + b1;

                for (int k = 0; k < K2; k++) {
                    const float w0 = __ldg(Wtail + (size_t)k * FD + colg);
                    const float w1 = __ldg(Wtail + (size_t)k * FD + colg + 1);
                    v0 += a2A[k] * w0; v1 += a2A[k] * w1;
                    v2 += a2B[k] * w0; v3 += a2B[k] * w1;
                }
                v0 = fmaxf(v0, 0.0f); v1 = fmaxf(v1, 0.0f);
                v2 = fmaxf(v2, 0.0f); v3 = fmaxf(v3, 0.0f);

                __nv_bfloat16 h0,h1,h2,h3,l0,l1,l2,l3;
                split2(v0,h0,l0); split2(v1,h1,l1);
                split2(v2,h2,l2); split2(v3,h3,l3);
                *(__nv_bfloat162*)(outHi + (size_t)rowA * FD + colg) = __nv_bfloat162(h0, h1);
                *(__nv_bfloat162*)(outLo + (size_t)rowA * FD + colg) = __nv_bfloat162(l0, l1);
                *(__nv_bfloat162*)(outHi + (size_t)rowB * FD + colg) = __nv_bfloat162(h2, h3);
                *(__nv_bfloat162*)(outLo + (size_t)rowB * FD + colg) = __nv_bfloat162(l2, l3);
            }
        }
    } else {
        // GEMM2 path: residual(A) + bias + relu, fused dot with w2 -> atomicAdd
        #pragma unroll
        for (int mt = 0; mt < 4; mt++) {
            const int rowA = m0 + warp_m * 64 + mt * 16 + qrow;
            const int rowB = rowA + 8;
            float sA = 0.0f, sB = 0.0f;

            #pragma unroll
            for (int nt = 0; nt < 4; nt++) {
                const int colg = n0 + warp_n * 32 + nt * 8 + qcol;
                const float b0 = __ldg(bias + colg), b1 = __ldg(bias + colg + 1);
                float v0 = c[mt][nt][0] + b0, v1 = c[mt][nt][1] + b1;
                float v2 = c[mt][nt][2] + b0, v3 = c[mt][nt][3] + b1;

                float2 hA = __bfloat1622float2(*(const __nv_bfloat162*)(Ahi + (size_t)rowA * FD + colg));
                float2 lA = __bfloat1622float2(*(const __nv_bfloat162*)(Alo + (size_t)rowA * FD + colg));
                float2 hB = __bfloat1622float2(*(const __nv_bfloat162*)(Ahi + (size_t)rowB * FD + colg));
                float2 lB = __bfloat1622float2(*(const __nv_bfloat162*)(Alo + (size_t)rowB * FD + colg));
                v0 += hA.x + lA.x; v1 += hA.y + lA.y;
                v2 += hB.x + lB.x; v3 += hB.y + lB.y;

                v0 = fmaxf(v0, 0.0f); v1 = fmaxf(v1, 0.0f);
                v2 = fmaxf(v2, 0.0f); v3 = fmaxf(v3, 0.0f);

                const float w0 = __ldg(w2 + colg), w1 = __ldg(w2 + colg + 1);
                sA += v0 * w0 + v1 * w1;
                sB += v2 * w0 + v3 * w1;
            }
            sA += __shfl_xor_sync(0xFFFFFFFFu, sA, 1);
            sA += __shfl_xor_sync(0xFFFFFFFFu, sA, 2);
            sB += __shfl_xor_sync(0xFFFFFFFFu, sB, 1);
            sB += __shfl_xor_sync(0xFFFFFFFFu, sB, 2);
            if ((lane & 3) == 0) {
                atomicAdd(dotOut + rowA, sA);
                atomicAdd(dotOut + rowB, sB);
            }
        }
    }
}

// ---------------------------------------------------------------------------
// Host orchestration
// ---------------------------------------------------------------------------
extern "C" void kernel_launch(void* const* d_in, const int* in_sizes, int n_in,
                              void* d_out, int out_size)
{
    const float* latent = (const float*)d_in[0];
    const float* rp     = (const float*)d_in[1];
    const float* w1[3] = {(const float*)d_in[2],  (const float*)d_in[8],  (const float*)d_in[14]};
    const float* b1[3] = {(const float*)d_in[3],  (const float*)d_in[9],  (const float*)d_in[15]};
    const float* wr[3] = {(const float*)d_in[4],  (const float*)d_in[10], (const float*)d_in[16]};
    const float* br[3] = {(const float*)d_in[5],  (const float*)d_in[11], (const float*)d_in[17]};
    const float* w2[3] = {(const float*)d_in[6],  (const float*)d_in[12], (const float*)d_in[18]};
    const float* b2[3] = {(const float*)d_in[7],  (const float*)d_in[13], (const float*)d_in[19]};

    float *feat, *std1, *std2;
    __nv_bfloat16 *lat_hi, *lat_lo, *h_hi, *h_lo, *w1T_hi, *w1T_lo, *wrT_hi, *wrT_lo;
    cudaGetSymbolAddress((void**)&feat,   g_feat);
    cudaGetSymbolAddress((void**)&lat_hi, g_lat_hi);
    cudaGetSymbolAddress((void**)&lat_lo, g_lat_lo);
    cudaGetSymbolAddress((void**)&h_hi,   g_h_hi);
    cudaGetSymbolAddress((void**)&h_lo,   g_h_lo);
    cudaGetSymbolAddress((void**)&std1,   g_std1);
    cudaGetSymbolAddress((void**)&std2,   g_std2);
    cudaGetSymbolAddress((void**)&w1T_hi, g_w1T_hi);
    cudaGetSymbolAddress((void**)&w1T_lo, g_w1T_lo);
    cudaGetSymbolAddress((void**)&wrT_hi, g_wrT_hi);
    cudaGetSymbolAddress((void**)&wrT_lo, g_wrT_lo);

    float* out = (float*)d_out;

    cudaFuncSetAttribute(gemm_mma_kernel, cudaFuncAttributeMaxDynamicSharedMemorySize, SMEM_TOTAL);

    const dim3 ggrid(FD / BN, MROWS / BM);   // (4, 256)
    const dim3 tgrid(16, 16);

    conv_split_kernel<<<2048, 256>>>(latent, lat_hi, lat_lo, MROWS * FD / 4);
    knn_feat_kernel<<<dim3(NPTS / 256, BATCH), 256>>>(rp, feat);

    const float* stdprev[3] = {nullptr, std1, std2};
    const float* a2s[3]     = {feat, std1, std2};
    const int    k2s[3]     = {12, 1, 1};
    float*       stdout_[3] = {std1, std2, out};

    for (int s = 0; s < 3; s++) {
        transW_kernel<<<tgrid, 256>>>(w1[s], w1T_hi, w1T_lo);
        gemm_mma_kernel<<<ggrid, 256, SMEM_TOTAL>>>(
            lat_hi, lat_lo, w1T_hi, w1T_lo, b1[s],
            a2s[s], k2s[s], w1[s] + (size_t)FD * FD,
            h_hi, h_lo, nullptr, nullptr);
        transW_kernel<<<tgrid, 256>>>(wr[s], wrT_hi, wrT_lo);
        init_out_kernel<<<MROWS / 256, 256>>>(stdprev[s], b2[s], stdout_[s]);
        gemm_mma_kernel<<<ggrid, 256, SMEM_TOTAL>>>(
            h_hi, h_lo, wrT_hi, wrT_lo, br[s],
            nullptr, 0, nullptr,
            nullptr, nullptr, w2[s], stdout_[s]);
    }
}

// round 6
// speedup vs baseline: 1.6849x; 1.1270x over previous
#include <cuda_runtime.h>
#include <cuda_bf16.h>
#include <cstdint>

#define BATCH 8
#define NPTS  4096
#define MROWS 32768
#define FD    512

// GEMM tiling
#define BM 128
#define BN 128
#define BK 32
#define ROWB 64                         // bytes per smem row (32 halves, no pad)
#define ARR_BYTES (BM * ROWB)           // 8192
#define STAGE_BYTES (4 * ARR_BYTES)     // 32768
#define NSTAGE 3
#define SMEM_TOTAL (NSTAGE * STAGE_BYTES)  // 98304

// ---------------------------------------------------------------------------
// Device scratch
// ---------------------------------------------------------------------------
__device__ float          g_feat[MROWS * 12];
__device__ __nv_bfloat16  g_lat_hi[MROWS * FD];
__device__ __nv_bfloat16  g_lat_lo[MROWS * FD];
__device__ __nv_bfloat16  g_h_hi[MROWS * FD];
__device__ __nv_bfloat16  g_h_lo[MROWS * FD];
__device__ float          g_std1[MROWS];
__device__ float          g_std2[MROWS];
__device__ __nv_bfloat16  g_w1T_hi[FD * FD];
__device__ __nv_bfloat16  g_w1T_lo[FD * FD];
__device__ __nv_bfloat16  g_wrT_hi[FD * FD];
__device__ __nv_bfloat16  g_wrT_lo[FD * FD];

// ---------------------------------------------------------------------------
// Helpers
// ---------------------------------------------------------------------------
__device__ __forceinline__ uint32_t smem_u32(const void* p) {
    uint32_t a;
    asm("{ .reg .u64 t; cvta.to.shared.u64 t, %1; cvt.u32.u64 %0, t; }" : "=r"(a) : "l"(p));
    return a;
}

__device__ __forceinline__ void cp16(uint32_t s, const void* g) {
    asm volatile("cp.async.cg.shared.global [%0], [%1], 16;" :: "r"(s), "l"(g));
}
__device__ __forceinline__ void cp_commit() { asm volatile("cp.async.commit_group;"); }
template <int N>
__device__ __forceinline__ void cp_wait() { asm volatile("cp.async.wait_group %0;" :: "n"(N)); }

__device__ __forceinline__ void ldmx4(uint32_t addr, uint32_t& r0, uint32_t& r1, uint32_t& r2, uint32_t& r3) {
    asm volatile("ldmatrix.sync.aligned.m8n8.x4.shared.b16 {%0,%1,%2,%3}, [%4];"
        : "=r"(r0), "=r"(r1), "=r"(r2), "=r"(r3) : "r"(addr));
}

__device__ __forceinline__ void mma_bf16(float* c, const uint32_t* a, const uint32_t* b) {
    asm volatile(
        "mma.sync.aligned.m16n8k16.row.col.f32.bf16.bf16.f32 "
        "{%0,%1,%2,%3}, {%4,%5,%6,%7}, {%8,%9}, {%0,%1,%2,%3};"
        : "+f"(c[0]), "+f"(c[1]), "+f"(c[2]), "+f"(c[3])
        : "r"(a[0]), "r"(a[1]), "r"(a[2]), "r"(a[3]), "r"(b[0]), "r"(b[1]));
}

__device__ __forceinline__ void split2(float x, __nv_bfloat16& h, __nv_bfloat16& l) {
    h = __float2bfloat16(x);
    l = __float2bfloat16(x - __bfloat162float(h));
}

// ---------------------------------------------------------------------------
// kNN + local covariance
// ---------------------------------------------------------------------------
__global__ __launch_bounds__(256) void knn_feat_kernel(
    const float* __restrict__ rp, float* __restrict__ feat)
{
    __shared__ float px[NPTS], py[NPTS], pz[NPTS];
    const int b = blockIdx.y;
    const float* base = rp + b * 3 * NPTS;
    for (int i = threadIdx.x; i < NPTS; i += 256) {
        px[i] = base[i]; py[i] = base[NPTS + i]; pz[i] = base[2 * NPTS + i];
    }
    __syncthreads();

    const int n = blockIdx.x * 256 + threadIdx.x;
    const float xi = px[n], yi = py[n], zi = pz[n];
    const float xxi = xi * xi + yi * yi + zi * zi;

    float bestv = -1e30f; int bestj = 0;
    for (int j = 0; j < NPTS; j++) {
        const float xj = px[j], yj = py[j], zj = pz[j];
        const float d = 2.0f * (xi * xj + yi * yj + zi * zj) - xxi - (xj * xj + yj * yj + zj * zj);
        if (j != n && d > bestv) { bestv = d; bestj = j; }
    }
    const float nx = px[bestj], ny = py[bestj], nz = pz[bestj];
    float* f = feat + (size_t)(b * NPTS + n) * 12;
    f[0] = xi;      f[1] = yi;      f[2] = zi;
    f[3] = xi * nx; f[4] = xi * ny; f[5] = xi * nz;
    f[6] = yi * nx; f[7] = yi * ny; f[8] = yi * nz;
    f[9] = zi * nx; f[10] = zi * ny; f[11] = zi * nz;
}

// ---------------------------------------------------------------------------
// fp32 -> bf16 hi/lo split (bulk)
// ---------------------------------------------------------------------------
__global__ __launch_bounds__(256) void conv_split_kernel(
    const float* __restrict__ x, __nv_bfloat16* __restrict__ hi,
    __nv_bfloat16* __restrict__ lo, int n4)
{
    for (int i = blockIdx.x * 256 + threadIdx.x; i < n4; i += gridDim.x * 256) {
        float4 v = ((const float4*)x)[i];
        __nv_bfloat16 h0,h1,h2,h3,l0,l1,l2,l3;
        split2(v.x,h0,l0); split2(v.y,h1,l1); split2(v.z,h2,l2); split2(v.w,h3,l3);
        __nv_bfloat162* ph = (__nv_bfloat162*)hi + i * 2;
        __nv_bfloat162* pl = (__nv_bfloat162*)lo + i * 2;
        ph[0] = __nv_bfloat162(h0, h1); ph[1] = __nv_bfloat162(h2, h3);
        pl[0] = __nv_bfloat162(l0, l1); pl[1] = __nv_bfloat162(l2, l3);
    }
}

// ---------------------------------------------------------------------------
// W[512,512] (k-major) -> WT[n][k] bf16 hi/lo
// ---------------------------------------------------------------------------
__global__ __launch_bounds__(256) void transW_kernel(
    const float* __restrict__ W, __nv_bfloat16* __restrict__ th, __nv_bfloat16* __restrict__ tl)
{
    __shared__ float t[32][33];
    const int n0 = blockIdx.x * 32, k0 = blockIdx.y * 32;
    const int tx = threadIdx.x & 31, ty = threadIdx.x >> 5;
    #pragma unroll
    for (int i = 0; i < 4; i++)
        t[ty + i * 8][tx] = W[(size_t)(k0 + ty + i * 8) * FD + n0 + tx];
    __syncthreads();
    #pragma unroll
    for (int i = 0; i < 4; i++) {
        float v = t[tx][ty + i * 8];
        __nv_bfloat16 h, l; split2(v, h, l);
        size_t o = (size_t)(n0 + ty + i * 8) * FD + k0 + tx;
        th[o] = h; tl[o] = l;
    }
}

// ---------------------------------------------------------------------------
// out[row] = (prev ? prev[row] : 0) + b2[0]   (pre-init for fused dot atomics)
// ---------------------------------------------------------------------------
__global__ __launch_bounds__(256) void init_out_kernel(
    const float* __restrict__ prev, const float* __restrict__ b2, float* __restrict__ out)
{
    const int i = blockIdx.x * 256 + threadIdx.x;
    out[i] = (prev ? prev[i] : 0.0f) + b2[0];
}

// ---------------------------------------------------------------------------
// Split-bf16 mma.sync GEMM. 3-stage cp.async pipeline, swizzled smem,
// one barrier per K-chunk.
//  Mode 1 (dotOut == nullptr):  H = relu(A@B^T + A2@Wtail + bias) -> outHi/outLo
//  Mode 2 (dotOut != nullptr):  v = relu(A@B^T + A + bias); atomicAdd(dotOut, v@w2)
// ---------------------------------------------------------------------------
__global__ __launch_bounds__(256, 2) void gemm_mma_kernel(
    const __nv_bfloat16* __restrict__ Ahi, const __nv_bfloat16* __restrict__ Alo,
    const __nv_bfloat16* __restrict__ Bhi, const __nv_bfloat16* __restrict__ Blo,
    const float* __restrict__ bias,
    const float* __restrict__ A2, const int K2, const float* __restrict__ Wtail,
    __nv_bfloat16* __restrict__ outHi, __nv_bfloat16* __restrict__ outLo,
    const float* __restrict__ w2, float* __restrict__ dotOut)
{
    extern __shared__ __align__(16) char dsm[];
    const uint32_t sbase = smem_u32(dsm);

    const int tid = threadIdx.x;
    const int m0 = blockIdx.y * BM;
    const int n0 = blockIdx.x * BN;
    const int warp = tid >> 5, lane = tid & 31;
    const int warp_m = warp >> 2;          // 0..1 -> 64 rows
    const int warp_n = warp & 3;           // 0..3 -> 32 cols

    // ---- loader geometry (swizzled, 64B rows, 16B atoms) ----
    const int lr0 = tid >> 2;              // rows lr0 and lr0+64
    const int lkq = tid & 3;               // atom (8 halves)
    // swizzle: atom' = atom ^ ((row>>1)&3); rows lr0 and lr0+64 share swizzle
    const uint32_t so0 = (uint32_t)(lr0 * ROWB + ((lkq ^ ((lr0 >> 1) & 3)) << 4));
    const uint32_t so1 = so0 + 64 * ROWB;  // 4096

    // running global pointers (advance by BK per chunk)
    const __nv_bfloat16* pAhi = Ahi + (size_t)(m0 + lr0) * FD + lkq * 8;
    const __nv_bfloat16* pAlo = Alo + (size_t)(m0 + lr0) * FD + lkq * 8;
    const __nv_bfloat16* pBhi = Bhi + (size_t)(n0 + lr0) * FD + lkq * 8;
    const __nv_bfloat16* pBlo = Blo + (size_t)(n0 + lr0) * FD + lkq * 8;

    auto issue = [&](uint32_t st) {
        cp16(st + 0 * ARR_BYTES + so0, pAhi);
        cp16(st + 0 * ARR_BYTES + so1, pAhi + (size_t)64 * FD);
        cp16(st + 1 * ARR_BYTES + so0, pAlo);
        cp16(st + 1 * ARR_BYTES + so1, pAlo + (size_t)64 * FD);
        cp16(st + 2 * ARR_BYTES + so0, pBhi);
        cp16(st + 2 * ARR_BYTES + so1, pBhi + (size_t)64 * FD);
        cp16(st + 3 * ARR_BYTES + so0, pBlo);
        cp16(st + 3 * ARR_BYTES + so1, pBlo + (size_t)64 * FD);
        cp_commit();
        pAhi += BK; pAlo += BK; pBhi += BK; pBlo += BK;
    };

    // ---- fragment read offsets (loop-invariant; kk handled by ^32) ----
    const int arow = lane & 15;
    const int hi16 = lane >> 4;            // atom bit0 within k16 block
    uint32_t aoff[4], boff[2];
    #pragma unroll
    for (int mt = 0; mt < 4; mt++) {
        const int r = warp_m * 64 + mt * 16 + arow;
        aoff[mt] = (uint32_t)(r * ROWB + ((hi16 ^ ((r >> 1) & 3)) << 4));
    }
    #pragma unroll
    for (int pr = 0; pr < 2; pr++) {
        const int r = warp_n * 32 + pr * 16 + arow;
        boff[pr] = (uint32_t)(r * ROWB + ((hi16 ^ ((r >> 1) & 3)) << 4));
    }

    float c[4][4][4];
    #pragma unroll
    for (int i = 0; i < 4; i++)
        #pragma unroll
        for (int j = 0; j < 4; j++)
            #pragma unroll
            for (int q = 0; q < 4; q++) c[i][j][q] = 0.0f;

    auto compute = [&](uint32_t st) {
        #pragma unroll
        for (int kk = 0; kk < 2; kk++) {
            const uint32_t kx = (uint32_t)(kk << 5);   // XOR flips atom bit1
            uint32_t ah[4][4], al[4][4], bh[4][2], bl[4][2];
            #pragma unroll
            for (int mt = 0; mt < 4; mt++) {
                const uint32_t ad = st + (aoff[mt] ^ kx);
                ldmx4(ad + 0 * ARR_BYTES, ah[mt][0], ah[mt][1], ah[mt][2], ah[mt][3]);
                ldmx4(ad + 1 * ARR_BYTES, al[mt][0], al[mt][1], al[mt][2], al[mt][3]);
            }
            #pragma unroll
            for (int pr = 0; pr < 2; pr++) {
                const uint32_t bd = st + (boff[pr] ^ kx);
                uint32_t r0, r1, r2, r3;
                ldmx4(bd + 2 * ARR_BYTES, r0, r1, r2, r3);
                bh[2*pr][0] = r0; bh[2*pr][1] = r2; bh[2*pr+1][0] = r1; bh[2*pr+1][1] = r3;
                ldmx4(bd + 3 * ARR_BYTES, r0, r1, r2, r3);
                bl[2*pr][0] = r0; bl[2*pr][1] = r2; bl[2*pr+1][0] = r1; bl[2*pr+1][1] = r3;
            }
            #pragma unroll
            for (int mt = 0; mt < 4; mt++)
                #pragma unroll
                for (int nt = 0; nt < 4; nt++) {
                    mma_bf16(c[mt][nt], ah[mt], bh[nt]);
                    mma_bf16(c[mt][nt], al[mt], bh[nt]);
                    mma_bf16(c[mt][nt], ah[mt], bl[nt]);
                }
        }
    };

    // ---- 3-stage pipelined mainloop, one barrier per chunk ----
    issue(sbase + 0 * STAGE_BYTES);
    issue(sbase + 1 * STAGE_BYTES);

    uint32_t cst = sbase;                  // compute stage for chunk ch
    uint32_t ist = sbase + 2 * STAGE_BYTES; // issue stage for chunk ch+2

    #pragma unroll 1
    for (int ch = 0; ch < FD / BK; ch++) {
        cp_wait<1>();
        __syncthreads();
        if (ch + 2 < FD / BK) {
            issue(ist);
            ist += STAGE_BYTES;
            if (ist == sbase + NSTAGE * STAGE_BYTES) ist = sbase;
        }
        compute(cst);
        cst += STAGE_BYTES;
        if (cst == sbase + NSTAGE * STAGE_BYTES) cst = sbase;
    }

    // ---- epilogue ----
    const int qrow = lane >> 2;            // 0..7
    const int qcol = (lane & 3) * 2;       // 0,2,4,6

    if (dotOut == nullptr) {
        // GEMM1 path: K2 tail + bias + relu, store hi/lo bf16
        #pragma unroll
        for (int mt = 0; mt < 4; mt++) {
            const int rowA = m0 + warp_m * 64 + mt * 16 + qrow;
            const int rowB = rowA + 8;

            float a2A[12], a2B[12];
            for (int k = 0; k < K2; k++) {
                a2A[k] = __ldg(A2 + (size_t)rowA * K2 + k);
                a2B[k] = __ldg(A2 + (size_t)rowB * K2 + k);
            }

            #pragma unroll
            for (int nt = 0; nt < 4; nt++) {
                const int colg = n0 + warp_n * 32 + nt * 8 + qcol;
                const float b0 = __ldg(bias + colg), b1 = __ldg(bias + colg + 1);
                float v0 = c[mt][nt][0] + b0, v1 = c[mt][nt][1] + b1;
                float v2 = c[mt][nt][2] + b0, v3 = c[mt][nt][3] + b1;

                for (int k = 0; k < K2; k++) {
                    const float w0 = __ldg(Wtail + (size_t)k * FD + colg);
                    const float w1 = __ldg(Wtail + (size_t)k * FD + colg + 1);
                    v0 += a2A[k] * w0; v1 += a2A[k] * w1;
                    v2 += a2B[k] * w0; v3 += a2B[k] * w1;
                }
                v0 = fmaxf(v0, 0.0f); v1 = fmaxf(v1, 0.0f);
                v2 = fmaxf(v2, 0.0f); v3 = fmaxf(v3, 0.0f);

                __nv_bfloat16 h0,h1,h2,h3,l0,l1,l2,l3;
                split2(v0,h0,l0); split2(v1,h1,l1);
                split2(v2,h2,l2); split2(v3,h3,l3);
                *(__nv_bfloat162*)(outHi + (size_t)rowA * FD + colg) = __nv_bfloat162(h0, h1);
                *(__nv_bfloat162*)(outLo + (size_t)rowA * FD + colg) = __nv_bfloat162(l0, l1);
                *(__nv_bfloat162*)(outHi + (size_t)rowB * FD + colg) = __nv_bfloat162(h2, h3);
                *(__nv_bfloat162*)(outLo + (size_t)rowB * FD + colg) = __nv_bfloat162(l2, l3);
            }
        }
    } else {
        // GEMM2 path: residual(A) + bias + relu, fused dot with w2 -> atomicAdd
        #pragma unroll
        for (int mt = 0; mt < 4; mt++) {
            const int rowA = m0 + warp_m * 64 + mt * 16 + qrow;
            const int rowB = rowA + 8;
            float sA = 0.0f, sB = 0.0f;

            #pragma unroll
            for (int nt = 0; nt < 4; nt++) {
                const int colg = n0 + warp_n * 32 + nt * 8 + qcol;
                const float b0 = __ldg(bias + colg), b1 = __ldg(bias + colg + 1);
                float v0 = c[mt][nt][0] + b0, v1 = c[mt][nt][1] + b1;
                float v2 = c[mt][nt][2] + b0, v3 = c[mt][nt][3] + b1;

                float2 hA = __bfloat1622float2(*(const __nv_bfloat162*)(Ahi + (size_t)rowA * FD + colg));
                float2 lA = __bfloat1622float2(*(const __nv_bfloat162*)(Alo + (size_t)rowA * FD + colg));
                float2 hB = __bfloat1622float2(*(const __nv_bfloat162*)(Ahi + (size_t)rowB * FD + colg));
                float2 lB = __bfloat1622float2(*(const __nv_bfloat162*)(Alo + (size_t)rowB * FD + colg));
                v0 += hA.x + lA.x; v1 += hA.y + lA.y;
                v2 += hB.x + lB.x; v3 += hB.y + lB.y;

                v0 = fmaxf(v0, 0.0f); v1 = fmaxf(v1, 0.0f);
                v2 = fmaxf(v2, 0.0f); v3 = fmaxf(v3, 0.0f);

                const float w0 = __ldg(w2 + colg), w1 = __ldg(w2 + colg + 1);
                sA += v0 * w0 + v1 * w1;
                sB += v2 * w0 + v3 * w1;
            }
            sA += __shfl_xor_sync(0xFFFFFFFFu, sA, 1);
            sA += __shfl_xor_sync(0xFFFFFFFFu, sA, 2);
            sB += __shfl_xor_sync(0xFFFFFFFFu, sB, 1);
            sB += __shfl_xor_sync(0xFFFFFFFFu, sB, 2);
            if ((lane & 3) == 0) {
                atomicAdd(dotOut + rowA, sA);
                atomicAdd(dotOut + rowB, sB);
            }
        }
    }
}

// ---------------------------------------------------------------------------
// Host orchestration
// ---------------------------------------------------------------------------
extern "C" void kernel_launch(void* const* d_in, const int* in_sizes, int n_in,
                              void* d_out, int out_size)
{
    const float* latent = (const float*)d_in[0];
    const float* rp     = (const float*)d_in[1];
    const float* w1[3] = {(const float*)d_in[2],  (const float*)d_in[8],  (const float*)d_in[14]};
    const float* b1[3] = {(const float*)d_in[3],  (const float*)d_in[9],  (const float*)d_in[15]};
    const float* wr[3] = {(const float*)d_in[4],  (const float*)d_in[10], (const float*)d_in[16]};
    const float* br[3] = {(const float*)d_in[5],  (const float*)d_in[11], (const float*)d_in[17]};
    const float* w2[3] = {(const float*)d_in[6],  (const float*)d_in[12], (const float*)d_in[18]};
    const float* b2[3] = {(const float*)d_in[7],  (const float*)d_in[13], (const float*)d_in[19]};

    float *feat, *std1, *std2;
    __nv_bfloat16 *lat_hi, *lat_lo, *h_hi, *h_lo, *w1T_hi, *w1T_lo, *wrT_hi, *wrT_lo;
    cudaGetSymbolAddress((void**)&feat,   g_feat);
    cudaGetSymbolAddress((void**)&lat_hi, g_lat_hi);
    cudaGetSymbolAddress((void**)&lat_lo, g_lat_lo);
    cudaGetSymbolAddress((void**)&h_hi,   g_h_hi);
    cudaGetSymbolAddress((void**)&h_lo,   g_h_lo);
    cudaGetSymbolAddress((void**)&std1,   g_std1);
    cudaGetSymbolAddress((void**)&std2,   g_std2);
    cudaGetSymbolAddress((void**)&w1T_hi, g_w1T_hi);
    cudaGetSymbolAddress((void**)&w1T_lo, g_w1T_lo);
    cudaGetSymbolAddress((void**)&wrT_hi, g_wrT_hi);
    cudaGetSymbolAddress((void**)&wrT_lo, g_wrT_lo);

    float* out = (float*)d_out;

    cudaFuncSetAttribute(gemm_mma_kernel, cudaFuncAttributeMaxDynamicSharedMemorySize, SMEM_TOTAL);

    const dim3 ggrid(FD / BN, MROWS / BM);   // (4, 256)
    const dim3 tgrid(16, 16);

    conv_split_kernel<<<2048, 256>>>(latent, lat_hi, lat_lo, MROWS * FD / 4);
    knn_feat_kernel<<<dim3(NPTS / 256, BATCH), 256>>>(rp, feat);

    const float* stdprev[3] = {nullptr, std1, std2};
    const float* a2s[3]     = {feat, std1, std2};
    const int    k2s[3]     = {12, 1, 1};
    float*       stdout_[3] = {std1, std2, out};

    for (int s = 0; s < 3; s++) {
        transW_kernel<<<tgrid, 256>>>(w1[s], w1T_hi, w1T_lo);
        gemm_mma_kernel<<<ggrid, 256, SMEM_TOTAL>>>(
            lat_hi, lat_lo, w1T_hi, w1T_lo, b1[s],
            a2s[s], k2s[s], w1[s] + (size_t)FD * FD,
            h_hi, h_lo, nullptr, nullptr);
        transW_kernel<<<tgrid, 256>>>(wr[s], wrT_hi, wrT_lo);
        init_out_kernel<<<MROWS / 256, 256>>>(stdprev[s], b2[s], stdout_[s]);
        gemm_mma_kernel<<<ggrid, 256, SMEM_TOTAL>>>(
            h_hi, h_lo, wrT_hi, wrT_lo, br[s],
            nullptr, 0, nullptr,
            nullptr, nullptr, w2[s], stdout_[s]);
    }
}

// round 7
// speedup vs baseline: 2.2005x; 1.3061x over previous
#include <cuda_runtime.h>
#include <cuda_fp16.h>
#include <cstdint>

#define BATCH 8
#define NPTS  4096
#define MROWS 32768
#define FD    512

// GEMM tiling
#define BM 128
#define BN 128
#define BK 32
#define ROWB 64                         // bytes per smem row (32 halves, no pad)
#define ARR_BYTES (BM * ROWB)           // 8192
#define STAGE_BYTES (3 * ARR_BYTES)     // 24576 (Ahi, Alo, Bhi)
#define NSTAGE 4
#define SMEM_TOTAL (NSTAGE * STAGE_BYTES)  // 98304

// ---------------------------------------------------------------------------
// Device scratch
// ---------------------------------------------------------------------------
__device__ float  g_feat[MROWS * 12];
__device__ __half g_lat_hi[MROWS * FD];
__device__ __half g_lat_lo[MROWS * FD];
__device__ __half g_h_hi[MROWS * FD];
__device__ __half g_h_lo[MROWS * FD];
__device__ float  g_std1[MROWS];
__device__ float  g_std2[MROWS];
__device__ __half g_w1T_hi[FD * FD];
__device__ __half g_wrT_hi[FD * FD];

// ---------------------------------------------------------------------------
// Helpers
// ---------------------------------------------------------------------------
__device__ __forceinline__ uint32_t smem_u32(const void* p) {
    uint32_t a;
    asm("{ .reg .u64 t; cvta.to.shared.u64 t, %1; cvt.u32.u64 %0, t; }" : "=r"(a) : "l"(p));
    return a;
}

__device__ __forceinline__ void cp16(uint32_t s, const void* g) {
    asm volatile("cp.async.cg.shared.global [%0], [%1], 16;" :: "r"(s), "l"(g));
}
__device__ __forceinline__ void cp_commit() { asm volatile("cp.async.commit_group;"); }
template <int N>
__device__ __forceinline__ void cp_wait() { asm volatile("cp.async.wait_group %0;" :: "n"(N)); }

__device__ __forceinline__ void ldmx4(uint32_t addr, uint32_t& r0, uint32_t& r1, uint32_t& r2, uint32_t& r3) {
    asm volatile("ldmatrix.sync.aligned.m8n8.x4.shared.b16 {%0,%1,%2,%3}, [%4];"
        : "=r"(r0), "=r"(r1), "=r"(r2), "=r"(r3) : "r"(addr));
}

__device__ __forceinline__ void mma_f16(float* c, const uint32_t* a, const uint32_t* b) {
    asm volatile(
        "mma.sync.aligned.m16n8k16.row.col.f32.f16.f16.f32 "
        "{%0,%1,%2,%3}, {%4,%5,%6,%7}, {%8,%9}, {%0,%1,%2,%3};"
        : "+f"(c[0]), "+f"(c[1]), "+f"(c[2]), "+f"(c[3])
        : "r"(a[0]), "r"(a[1]), "r"(a[2]), "r"(a[3]), "r"(b[0]), "r"(b[1]));
}

__device__ __forceinline__ void split2h(float x, __half& h, __half& l) {
    h = __float2half_rn(x);
    l = __float2half_rn(x - __half2float(h));
}

// ---------------------------------------------------------------------------
// kNN + local covariance
// ---------------------------------------------------------------------------
__global__ __launch_bounds__(256) void knn_feat_kernel(
    const float* __restrict__ rp, float* __restrict__ feat)
{
    __shared__ float px[NPTS], py[NPTS], pz[NPTS];
    const int b = blockIdx.y;
    const float* base = rp + b * 3 * NPTS;
    for (int i = threadIdx.x; i < NPTS; i += 256) {
        px[i] = base[i]; py[i] = base[NPTS + i]; pz[i] = base[2 * NPTS + i];
    }
    __syncthreads();

    const int n = blockIdx.x * 256 + threadIdx.x;
    const float xi = px[n], yi = py[n], zi = pz[n];
    const float xxi = xi * xi + yi * yi + zi * zi;

    float bestv = -1e30f; int bestj = 0;
    for (int j = 0; j < NPTS; j++) {
        const float xj = px[j], yj = py[j], zj = pz[j];
        const float d = 2.0f * (xi * xj + yi * yj + zi * zj) - xxi - (xj * xj + yj * yj + zj * zj);
        if (j != n && d > bestv) { bestv = d; bestj = j; }
    }
    const float nx = px[bestj], ny = py[bestj], nz = pz[bestj];
    float* f = feat + (size_t)(b * NPTS + n) * 12;
    f[0] = xi;      f[1] = yi;      f[2] = zi;
    f[3] = xi * nx; f[4] = xi * ny; f[5] = xi * nz;
    f[6] = yi * nx; f[7] = yi * ny; f[8] = yi * nz;
    f[9] = zi * nx; f[10] = zi * ny; f[11] = zi * nz;
}

// ---------------------------------------------------------------------------
// fp32 -> fp16 hi/lo split (bulk)
// ---------------------------------------------------------------------------
__global__ __launch_bounds__(256) void conv_split_kernel(
    const float* __restrict__ x, __half* __restrict__ hi,
    __half* __restrict__ lo, int n4)
{
    for (int i = blockIdx.x * 256 + threadIdx.x; i < n4; i += gridDim.x * 256) {
        float4 v = ((const float4*)x)[i];
        __half h0,h1,h2,h3,l0,l1,l2,l3;
        split2h(v.x,h0,l0); split2h(v.y,h1,l1); split2h(v.z,h2,l2); split2h(v.w,h3,l3);
        __half2* ph = (__half2*)hi + i * 2;
        __half2* pl = (__half2*)lo + i * 2;
        ph[0] = __halves2half2(h0, h1); ph[1] = __halves2half2(h2, h3);
        pl[0] = __halves2half2(l0, l1); pl[1] = __halves2half2(l2, l3);
    }
}

// ---------------------------------------------------------------------------
// W[512,512] (k-major) -> WT[n][k] fp16 (hi only; B side uncorrected)
// ---------------------------------------------------------------------------
__global__ __launch_bounds__(256) void transW_kernel(
    const float* __restrict__ W, __half* __restrict__ th)
{
    __shared__ float t[32][33];
    const int n0 = blockIdx.x * 32, k0 = blockIdx.y * 32;
    const int tx = threadIdx.x & 31, ty = threadIdx.x >> 5;
    #pragma unroll
    for (int i = 0; i < 4; i++)
        t[ty + i * 8][tx] = W[(size_t)(k0 + ty + i * 8) * FD + n0 + tx];
    __syncthreads();
    #pragma unroll
    for (int i = 0; i < 4; i++) {
        size_t o = (size_t)(n0 + ty + i * 8) * FD + k0 + tx;
        th[o] = __float2half_rn(t[tx][ty + i * 8]);
    }
}

// ---------------------------------------------------------------------------
// out[row] = (prev ? prev[row] : 0) + b2[0]   (pre-init for fused dot atomics)
// ---------------------------------------------------------------------------
__global__ __launch_bounds__(256) void init_out_kernel(
    const float* __restrict__ prev, const float* __restrict__ b2, float* __restrict__ out)
{
    const int i = blockIdx.x * 256 + threadIdx.x;
    out[i] = (prev ? prev[i] : 0.0f) + b2[0];
}

// ---------------------------------------------------------------------------
// Split-fp16 mma.sync GEMM: C = (Ahi+Alo) @ Bhi^T, fp32 accum.
// 4-stage cp.async pipeline, swizzled smem, one barrier per K-chunk.
//  Mode 1 (dotOut == nullptr):  H = relu(C + A2@Wtail + bias) -> outHi/outLo
//  Mode 2 (dotOut != nullptr):  v = relu(C + A + bias); atomicAdd(dotOut, v@w2)
// ---------------------------------------------------------------------------
__global__ __launch_bounds__(256, 2) void gemm_mma_kernel(
    const __half* __restrict__ Ahi, const __half* __restrict__ Alo,
    const __half* __restrict__ Bhi,
    const float* __restrict__ bias,
    const float* __restrict__ A2, const int K2, const float* __restrict__ Wtail,
    __half* __restrict__ outHi, __half* __restrict__ outLo,
    const float* __restrict__ w2, float* __restrict__ dotOut)
{
    extern __shared__ __align__(16) char dsm[];
    const uint32_t sbase = smem_u32(dsm);

    const int tid = threadIdx.x;
    const int m0 = blockIdx.y * BM;
    const int n0 = blockIdx.x * BN;
    const int warp = tid >> 5, lane = tid & 31;
    const int warp_m = warp >> 2;          // 0..1 -> 64 rows
    const int warp_n = warp & 3;           // 0..3 -> 32 cols

    // ---- loader geometry (swizzled, 64B rows, 16B atoms) ----
    const int lr0 = tid >> 2;              // rows lr0 and lr0+64
    const int lkq = tid & 3;               // atom (8 halves)
    const uint32_t so0 = (uint32_t)(lr0 * ROWB + ((lkq ^ ((lr0 >> 1) & 3)) << 4));
    const uint32_t so1 = so0 + 64 * ROWB;  // 4096

    const __half* pAhi = Ahi + (size_t)(m0 + lr0) * FD + lkq * 8;
    const __half* pAlo = Alo + (size_t)(m0 + lr0) * FD + lkq * 8;
    const __half* pBhi = Bhi + (size_t)(n0 + lr0) * FD + lkq * 8;

    auto issue = [&](uint32_t st) {
        cp16(st + 0 * ARR_BYTES + so0, pAhi);
        cp16(st + 0 * ARR_BYTES + so1, pAhi + (size_t)64 * FD);
        cp16(st + 1 * ARR_BYTES + so0, pAlo);
        cp16(st + 1 * ARR_BYTES + so1, pAlo + (size_t)64 * FD);
        cp16(st + 2 * ARR_BYTES + so0, pBhi);
        cp16(st + 2 * ARR_BYTES + so1, pBhi + (size_t)64 * FD);
        cp_commit();
        pAhi += BK; pAlo += BK; pBhi += BK;
    };

    // ---- fragment read offsets (loop-invariant; kk handled by ^32) ----
    const int arow = lane & 15;
    const int hi16 = lane >> 4;
    uint32_t aoff[4], boff[2];
    #pragma unroll
    for (int mt = 0; mt < 4; mt++) {
        const int r = warp_m * 64 + mt * 16 + arow;
        aoff[mt] = (uint32_t)(r * ROWB + ((hi16 ^ ((r >> 1) & 3)) << 4));
    }
    #pragma unroll
    for (int pr = 0; pr < 2; pr++) {
        const int r = warp_n * 32 + pr * 16 + arow;
        boff[pr] = (uint32_t)(r * ROWB + ((hi16 ^ ((r >> 1) & 3)) << 4));
    }

    float c[4][4][4];
    #pragma unroll
    for (int i = 0; i < 4; i++)
        #pragma unroll
        for (int j = 0; j < 4; j++)
            #pragma unroll
            for (int q = 0; q < 4; q++) c[i][j][q] = 0.0f;

    auto compute = [&](uint32_t st) {
        #pragma unroll
        for (int kk = 0; kk < 2; kk++) {
            const uint32_t kx = (uint32_t)(kk << 5);
            uint32_t ah[4][4], al[4][4], bh[4][2];
            #pragma unroll
            for (int mt = 0; mt < 4; mt++) {
                const uint32_t ad = st + (aoff[mt] ^ kx);
                ldmx4(ad + 0 * ARR_BYTES, ah[mt][0], ah[mt][1], ah[mt][2], ah[mt][3]);
                ldmx4(ad + 1 * ARR_BYTES, al[mt][0], al[mt][1], al[mt][2], al[mt][3]);
            }
            #pragma unroll
            for (int pr = 0; pr < 2; pr++) {
                const uint32_t bd = st + (boff[pr] ^ kx);
                uint32_t r0, r1, r2, r3;
                ldmx4(bd + 2 * ARR_BYTES, r0, r1, r2, r3);
                bh[2*pr][0] = r0; bh[2*pr][1] = r2; bh[2*pr+1][0] = r1; bh[2*pr+1][1] = r3;
            }
            #pragma unroll
            for (int mt = 0; mt < 4; mt++)
                #pragma unroll
                for (int nt = 0; nt < 4; nt++) {
                    mma_f16(c[mt][nt], ah[mt], bh[nt]);
                    mma_f16(c[mt][nt], al[mt], bh[nt]);
                }
        }
    };

    // ---- 4-stage pipelined mainloop, one barrier per chunk ----
    issue(sbase + 0 * STAGE_BYTES);
    issue(sbase + 1 * STAGE_BYTES);
    issue(sbase + 2 * STAGE_BYTES);

    uint32_t cst = sbase;                   // compute stage for chunk ch
    uint32_t ist = sbase + 3 * STAGE_BYTES; // issue stage for chunk ch+3

    #pragma unroll 1
    for (int ch = 0; ch < FD / BK; ch++) {
        cp_wait<2>();
        __syncthreads();
        if (ch + 3 < FD / BK) {
            issue(ist);
            ist += STAGE_BYTES;
            if (ist == sbase + NSTAGE * STAGE_BYTES) ist = sbase;
        }
        compute(cst);
        cst += STAGE_BYTES;
        if (cst == sbase + NSTAGE * STAGE_BYTES) cst = sbase;
    }

    // ---- epilogue ----
    const int qrow = lane >> 2;            // 0..7
    const int qcol = (lane & 3) * 2;       // 0,2,4,6

    if (dotOut == nullptr) {
        // GEMM1 path: K2 tail + bias + relu, store hi/lo fp16
        #pragma unroll
        for (int mt = 0; mt < 4; mt++) {
            const int rowA = m0 + warp_m * 64 + mt * 16 + qrow;
            const int rowB = rowA + 8;

            float a2A[12], a2B[12];
            for (int k = 0; k < K2; k++) {
                a2A[k] = __ldg(A2 + (size_t)rowA * K2 + k);
                a2B[k] = __ldg(A2 + (size_t)rowB * K2 + k);
            }

            #pragma unroll
            for (int nt = 0; nt < 4; nt++) {
                const int colg = n0 + warp_n * 32 + nt * 8 + qcol;
                const float b0 = __ldg(bias + colg), b1 = __ldg(bias + colg + 1);
                float v0 = c[mt][nt][0] + b0, v1 = c[mt][nt][1] + b1;
                float v2 = c[mt][nt][2] + b0, v3 = c[mt][nt][3] + b1;

                for (int k = 0; k < K2; k++) {
                    const float w0 = __ldg(Wtail + (size_t)k * FD + colg);
                    const float w1 = __ldg(Wtail + (size_t)k * FD + colg + 1);
                    v0 += a2A[k] * w0; v1 += a2A[k] * w1;
                    v2 += a2B[k] * w0; v3 += a2B[k] * w1;
                }
                v0 = fmaxf(v0, 0.0f); v1 = fmaxf(v1, 0.0f);
                v2 = fmaxf(v2, 0.0f); v3 = fmaxf(v3, 0.0f);

                __half h0,h1,h2,h3,l0,l1,l2,l3;
                split2h(v0,h0,l0); split2h(v1,h1,l1);
                split2h(v2,h2,l2); split2h(v3,h3,l3);
                *(__half2*)(outHi + (size_t)rowA * FD + colg) = __halves2half2(h0, h1);
                *(__half2*)(outLo + (size_t)rowA * FD + colg) = __halves2half2(l0, l1);
                *(__half2*)(outHi + (size_t)rowB * FD + colg) = __halves2half2(h2, h3);
                *(__half2*)(outLo + (size_t)rowB * FD + colg) = __halves2half2(l2, l3);
            }
        }
    } else {
        // GEMM2 path: residual(A) + bias + relu, fused dot with w2 -> atomicAdd
        #pragma unroll
        for (int mt = 0; mt < 4; mt++) {
            const int rowA = m0 + warp_m * 64 + mt * 16 + qrow;
            const int rowB = rowA + 8;
            float sA = 0.0f, sB = 0.0f;

            #pragma unroll
            for (int nt = 0; nt < 4; nt++) {
                const int colg = n0 + warp_n * 32 + nt * 8 + qcol;
                const float b0 = __ldg(bias + colg), b1 = __ldg(bias + colg + 1);
                float v0 = c[mt][nt][0] + b0, v1 = c[mt][nt][1] + b1;
                float v2 = c[mt][nt][2] + b0, v3 = c[mt][nt][3] + b1;

                float2 hA = __half22float2(*(const __half2*)(Ahi + (size_t)rowA * FD + colg));
                float2 lA = __half22float2(*(const __half2*)(Alo + (size_t)rowA * FD + colg));
                float2 hB = __half22float2(*(const __half2*)(Ahi + (size_t)rowB * FD + colg));
                float2 lB = __half22float2(*(const __half2*)(Alo + (size_t)rowB * FD + colg));
                v0 += hA.x + lA.x; v1 += hA.y + lA.y;
                v2 += hB.x + lB.x; v3 += hB.y + lB.y;

                v0 = fmaxf(v0, 0.0f); v1 = fmaxf(v1, 0.0f);
                v2 = fmaxf(v2, 0.0f); v3 = fmaxf(v3, 0.0f);

                const float w0 = __ldg(w2 + colg), w1 = __ldg(w2 + colg + 1);
                sA += v0 * w0 + v1 * w1;
                sB += v2 * w0 + v3 * w1;
            }
            sA += __shfl_xor_sync(0xFFFFFFFFu, sA, 1);
            sA += __shfl_xor_sync(0xFFFFFFFFu, sA, 2);
            sB += __shfl_xor_sync(0xFFFFFFFFu, sB, 1);
            sB += __shfl_xor_sync(0xFFFFFFFFu, sB, 2);
            if ((lane & 3) == 0) {
                atomicAdd(dotOut + rowA, sA);
                atomicAdd(dotOut + rowB, sB);
            }
        }
    }
}

// ---------------------------------------------------------------------------
// Host orchestration
// ---------------------------------------------------------------------------
extern "C" void kernel_launch(void* const* d_in, const int* in_sizes, int n_in,
                              void* d_out, int out_size)
{
    const float* latent = (const float*)d_in[0];
    const float* rp     = (const float*)d_in[1];
    const float* w1[3] = {(const float*)d_in[2],  (const float*)d_in[8],  (const float*)d_in[14]};
    const float* b1[3] = {(const float*)d_in[3],  (const float*)d_in[9],  (const float*)d_in[15]};
    const float* wr[3] = {(const float*)d_in[4],  (const float*)d_in[10], (const float*)d_in[16]};
    const float* br[3] = {(const float*)d_in[5],  (const float*)d_in[11], (const float*)d_in[17]};
    const float* w2[3] = {(const float*)d_in[6],  (const float*)d_in[12], (const float*)d_in[18]};
    const float* b2[3] = {(const float*)d_in[7],  (const float*)d_in[13], (const float*)d_in[19]};

    float *feat, *std1, *std2;
    __half *lat_hi, *lat_lo, *h_hi, *h_lo, *w1T_hi, *wrT_hi;
    cudaGetSymbolAddress((void**)&feat,   g_feat);
    cudaGetSymbolAddress((void**)&lat_hi, g_lat_hi);
    cudaGetSymbolAddress((void**)&lat_lo, g_lat_lo);
    cudaGetSymbolAddress((void**)&h_hi,   g_h_hi);
    cudaGetSymbolAddress((void**)&h_lo,   g_h_lo);
    cudaGetSymbolAddress((void**)&std1,   g_std1);
    cudaGetSymbolAddress((void**)&std2,   g_std2);
    cudaGetSymbolAddress((void**)&w1T_hi, g_w1T_hi);
    cudaGetSymbolAddress((void**)&wrT_hi, g_wrT_hi);

    float* out = (float*)d_out;

    cudaFuncSetAttribute(gemm_mma_kernel, cudaFuncAttributeMaxDynamicSharedMemorySize, SMEM_TOTAL);

    const dim3 ggrid(FD / BN, MROWS / BM);   // (4, 256)
    const dim3 tgrid(16, 16);

    conv_split_kernel<<<2048, 256>>>(latent, lat_hi, lat_lo, MROWS * FD / 4);
    knn_feat_kernel<<<dim3(NPTS / 256, BATCH), 256>>>(rp, feat);

    const float* stdprev[3] = {nullptr, std1, std2};
    const float* a2s[3]     = {feat, std1, std2};
    const int    k2s[3]     = {12, 1, 1};
    float*       stdout_[3] = {std1, std2, out};

    for (int s = 0; s < 3; s++) {
        transW_kernel<<<tgrid, 256>>>(w1[s], w1T_hi);
        gemm_mma_kernel<<<ggrid, 256, SMEM_TOTAL>>>(
            lat_hi, lat_lo, w1T_hi, b1[s],
            a2s[s], k2s[s], w1[s] + (size_t)FD * FD,
            h_hi, h_lo, nullptr, nullptr);
        transW_kernel<<<tgrid, 256>>>(wr[s], wrT_hi);
        init_out_kernel<<<MROWS / 256, 256>>>(stdprev[s], b2[s], stdout_[s]);
        gemm_mma_kernel<<<ggrid, 256, SMEM_TOTAL>>>(
            h_hi, h_lo, wrT_hi, br[s],
            nullptr, 0, nullptr,
            nullptr, nullptr, w2[s], stdout_[s]);
    }
}

// round 8
// speedup vs baseline: 2.3853x; 1.0840x over previous
#include <cuda_runtime.h>
#include <cuda_fp16.h>
#include <cstdint>

#define BATCH 8
#define NPTS  4096
#define MROWS 32768
#define FD    512

// GEMM tiling
#define BM 128
#define BN 128
#define BK 32
#define ROWB 64                         // bytes per smem row (32 halves, no pad)
#define ARR_BYTES (BM * ROWB)           // 8192
#define STAGE_BYTES (3 * ARR_BYTES)     // 24576 (A, Bhi, Blo)
#define NSTAGE 4
#define SMEM_TOTAL (NSTAGE * STAGE_BYTES)  // 98304

// ---------------------------------------------------------------------------
// Device scratch
// ---------------------------------------------------------------------------
__device__ float  g_feat[MROWS * 12];
__device__ __half g_lat[MROWS * FD];
__device__ __half g_h[MROWS * FD];
__device__ float  g_std1[MROWS];
__device__ float  g_std2[MROWS];
__device__ __half g_w1T_hi[FD * FD];
__device__ __half g_w1T_lo[FD * FD];
__device__ __half g_wrT_hi[FD * FD];
__device__ __half g_wrT_lo[FD * FD];

// ---------------------------------------------------------------------------
// Helpers
// ---------------------------------------------------------------------------
__device__ __forceinline__ uint32_t smem_u32(const void* p) {
    uint32_t a;
    asm("{ .reg .u64 t; cvta.to.shared.u64 t, %1; cvt.u32.u64 %0, t; }" : "=r"(a) : "l"(p));
    return a;
}

__device__ __forceinline__ void cp16(uint32_t s, const void* g) {
    asm volatile("cp.async.cg.shared.global [%0], [%1], 16;" :: "r"(s), "l"(g));
}
__device__ __forceinline__ void cp_commit() { asm volatile("cp.async.commit_group;"); }
template <int N>
__device__ __forceinline__ void cp_wait() { asm volatile("cp.async.wait_group %0;" :: "n"(N)); }

__device__ __forceinline__ void ldmx4(uint32_t addr, uint32_t& r0, uint32_t& r1, uint32_t& r2, uint32_t& r3) {
    asm volatile("ldmatrix.sync.aligned.m8n8.x4.shared.b16 {%0,%1,%2,%3}, [%4];"
        : "=r"(r0), "=r"(r1), "=r"(r2), "=r"(r3) : "r"(addr));
}

__device__ __forceinline__ void mma_f16(float* c, const uint32_t* a, const uint32_t* b) {
    asm volatile(
        "mma.sync.aligned.m16n8k16.row.col.f32.f16.f16.f32 "
        "{%0,%1,%2,%3}, {%4,%5,%6,%7}, {%8,%9}, {%0,%1,%2,%3};"
        : "+f"(c[0]), "+f"(c[1]), "+f"(c[2]), "+f"(c[3])
        : "r"(a[0]), "r"(a[1]), "r"(a[2]), "r"(a[3]), "r"(b[0]), "r"(b[1]));
}

__device__ __forceinline__ void split2h(float x, __half& h, __half& l) {
    h = __float2half_rn(x);
    l = __float2half_rn(x - __half2float(h));
}

// ---------------------------------------------------------------------------
// kNN + local covariance
// ---------------------------------------------------------------------------
__global__ __launch_bounds__(256) void knn_feat_kernel(
    const float* __restrict__ rp, float* __restrict__ feat)
{
    __shared__ float px[NPTS], py[NPTS], pz[NPTS];
    const int b = blockIdx.y;
    const float* base = rp + b * 3 * NPTS;
    for (int i = threadIdx.x; i < NPTS; i += 256) {
        px[i] = base[i]; py[i] = base[NPTS + i]; pz[i] = base[2 * NPTS + i];
    }
    __syncthreads();

    const int n = blockIdx.x * 256 + threadIdx.x;
    const float xi = px[n], yi = py[n], zi = pz[n];
    const float xxi = xi * xi + yi * yi + zi * zi;

    float bestv = -1e30f; int bestj = 0;
    for (int j = 0; j < NPTS; j++) {
        const float xj = px[j], yj = py[j], zj = pz[j];
        const float d = 2.0f * (xi * xj + yi * yj + zi * zj) - xxi - (xj * xj + yj * yj + zj * zj);
        if (j != n && d > bestv) { bestv = d; bestj = j; }
    }
    const float nx = px[bestj], ny = py[bestj], nz = pz[bestj];
    float* f = feat + (size_t)(b * NPTS + n) * 12;
    f[0] = xi;      f[1] = yi;      f[2] = zi;
    f[3] = xi * nx; f[4] = xi * ny; f[5] = xi * nz;
    f[6] = yi * nx; f[7] = yi * ny; f[8] = yi * nz;
    f[9] = zi * nx; f[10] = zi * ny; f[11] = zi * nz;
}

// ---------------------------------------------------------------------------
// fp32 -> fp16 convert (bulk, activations; no split needed — B is corrected)
// ---------------------------------------------------------------------------
__global__ __launch_bounds__(256) void conv_h_kernel(
    const float* __restrict__ x, __half* __restrict__ o, int n4)
{
    for (int i = blockIdx.x * 256 + threadIdx.x; i < n4; i += gridDim.x * 256) {
        float4 v = ((const float4*)x)[i];
        __half2* p = (__half2*)o + i * 2;
        p[0] = __halves2half2(__float2half_rn(v.x), __float2half_rn(v.y));
        p[1] = __halves2half2(__float2half_rn(v.z), __float2half_rn(v.w));
    }
}

// ---------------------------------------------------------------------------
// W[512,512] (k-major) -> WT[n][k] fp16 hi/lo
// ---------------------------------------------------------------------------
__global__ __launch_bounds__(256) void transW_kernel(
    const float* __restrict__ W, __half* __restrict__ th, __half* __restrict__ tl)
{
    __shared__ float t[32][33];
    const int n0 = blockIdx.x * 32, k0 = blockIdx.y * 32;
    const int tx = threadIdx.x & 31, ty = threadIdx.x >> 5;
    #pragma unroll
    for (int i = 0; i < 4; i++)
        t[ty + i * 8][tx] = W[(size_t)(k0 + ty + i * 8) * FD + n0 + tx];
    __syncthreads();
    #pragma unroll
    for (int i = 0; i < 4; i++) {
        float v = t[tx][ty + i * 8];
        __half h, l; split2h(v, h, l);
        size_t o = (size_t)(n0 + ty + i * 8) * FD + k0 + tx;
        th[o] = h; tl[o] = l;
    }
}

// ---------------------------------------------------------------------------
// out[row] = (prev ? prev[row] : 0) + b2[0]   (pre-init for fused dot atomics)
// ---------------------------------------------------------------------------
__global__ __launch_bounds__(256) void init_out_kernel(
    const float* __restrict__ prev, const float* __restrict__ b2, float* __restrict__ out)
{
    const int i = blockIdx.x * 256 + threadIdx.x;
    out[i] = (prev ? prev[i] : 0.0f) + b2[0];
}

// ---------------------------------------------------------------------------
// Split-B fp16 mma.sync GEMM: C = A @ (Bhi+Blo)^T, fp32 accum.
// 4-stage cp.async pipeline, swizzled smem, one barrier per K-chunk.
//  Mode 1 (dotOut == nullptr):  H = relu(C + A2@Wtail + bias) -> outH (fp16)
//  Mode 2 (dotOut != nullptr):  v = relu(C + A + bias); atomicAdd(dotOut, v@w2)
// ---------------------------------------------------------------------------
__global__ __launch_bounds__(256, 2) void gemm_mma_kernel(
    const __half* __restrict__ A,
    const __half* __restrict__ Bhi, const __half* __restrict__ Blo,
    const float* __restrict__ bias,
    const float* __restrict__ A2, const int K2, const float* __restrict__ Wtail,
    __half* __restrict__ outH,
    const float* __restrict__ w2, float* __restrict__ dotOut)
{
    extern __shared__ __align__(16) char dsm[];
    const uint32_t sbase = smem_u32(dsm);

    const int tid = threadIdx.x;
    const int m0 = blockIdx.y * BM;
    const int n0 = blockIdx.x * BN;
    const int warp = tid >> 5, lane = tid & 31;
    const int warp_m = warp >> 2;          // 0..1 -> 64 rows
    const int warp_n = warp & 3;           // 0..3 -> 32 cols

    // ---- loader geometry (swizzled, 64B rows, 16B atoms) ----
    const int lr0 = tid >> 2;              // rows lr0 and lr0+64
    const int lkq = tid & 3;               // atom (8 halves)
    const uint32_t so0 = (uint32_t)(lr0 * ROWB + ((lkq ^ ((lr0 >> 1) & 3)) << 4));
    const uint32_t so1 = so0 + 64 * ROWB;  // 4096

    const __half* pA   = A   + (size_t)(m0 + lr0) * FD + lkq * 8;
    const __half* pBhi = Bhi + (size_t)(n0 + lr0) * FD + lkq * 8;
    const __half* pBlo = Blo + (size_t)(n0 + lr0) * FD + lkq * 8;

    auto issue = [&](uint32_t st) {
        cp16(st + 0 * ARR_BYTES + so0, pA);
        cp16(st + 0 * ARR_BYTES + so1, pA + (size_t)64 * FD);
        cp16(st + 1 * ARR_BYTES + so0, pBhi);
        cp16(st + 1 * ARR_BYTES + so1, pBhi + (size_t)64 * FD);
        cp16(st + 2 * ARR_BYTES + so0, pBlo);
        cp16(st + 2 * ARR_BYTES + so1, pBlo + (size_t)64 * FD);
        cp_commit();
        pA += BK; pBhi += BK; pBlo += BK;
    };

    // ---- fragment read offsets (loop-invariant; kk handled by ^32) ----
    const int arow = lane & 15;
    const int hi16 = lane >> 4;
    uint32_t aoff[4], boff[2];
    #pragma unroll
    for (int mt = 0; mt < 4; mt++) {
        const int r = warp_m * 64 + mt * 16 + arow;
        aoff[mt] = (uint32_t)(r * ROWB + ((hi16 ^ ((r >> 1) & 3)) << 4));
    }
    #pragma unroll
    for (int pr = 0; pr < 2; pr++) {
        const int r = warp_n * 32 + pr * 16 + arow;
        boff[pr] = (uint32_t)(r * ROWB + ((hi16 ^ ((r >> 1) & 3)) << 4));
    }

    float c[4][4][4];
    #pragma unroll
    for (int i = 0; i < 4; i++)
        #pragma unroll
        for (int j = 0; j < 4; j++)
            #pragma unroll
            for (int q = 0; q < 4; q++) c[i][j][q] = 0.0f;

    auto compute = [&](uint32_t st) {
        #pragma unroll
        for (int kk = 0; kk < 2; kk++) {
            const uint32_t kx = (uint32_t)(kk << 5);
            uint32_t a[4][4], bh[4][2], bl[4][2];
            #pragma unroll
            for (int mt = 0; mt < 4; mt++) {
                const uint32_t ad = st + (aoff[mt] ^ kx);
                ldmx4(ad + 0 * ARR_BYTES, a[mt][0], a[mt][1], a[mt][2], a[mt][3]);
            }
            #pragma unroll
            for (int pr = 0; pr < 2; pr++) {
                const uint32_t bd = st + (boff[pr] ^ kx);
                uint32_t r0, r1, r2, r3;
                ldmx4(bd + 1 * ARR_BYTES, r0, r1, r2, r3);
                bh[2*pr][0] = r0; bh[2*pr][1] = r2; bh[2*pr+1][0] = r1; bh[2*pr+1][1] = r3;
                ldmx4(bd + 2 * ARR_BYTES, r0, r1, r2, r3);
                bl[2*pr][0] = r0; bl[2*pr][1] = r2; bl[2*pr+1][0] = r1; bl[2*pr+1][1] = r3;
            }
            // 16 independent hi-products, then 16 independent lo-products
            #pragma unroll
            for (int mt = 0; mt < 4; mt++)
                #pragma unroll
                for (int nt = 0; nt < 4; nt++)
                    mma_f16(c[mt][nt], a[mt], bh[nt]);
            #pragma unroll
            for (int mt = 0; mt < 4; mt++)
                #pragma unroll
                for (int nt = 0; nt < 4; nt++)
                    mma_f16(c[mt][nt], a[mt], bl[nt]);
        }
    };

    // ---- 4-stage pipelined mainloop, one barrier per chunk ----
    issue(sbase + 0 * STAGE_BYTES);
    issue(sbase + 1 * STAGE_BYTES);
    issue(sbase + 2 * STAGE_BYTES);

    uint32_t cst = sbase;                   // compute stage for chunk ch
    uint32_t ist = sbase + 3 * STAGE_BYTES; // issue stage for chunk ch+3

    #pragma unroll 1
    for (int ch = 0; ch < FD / BK; ch++) {
        cp_wait<2>();
        __syncthreads();
        if (ch + 3 < FD / BK) {
            issue(ist);
            ist += STAGE_BYTES;
            if (ist == sbase + NSTAGE * STAGE_BYTES) ist = sbase;
        }
        compute(cst);
        cst += STAGE_BYTES;
        if (cst == sbase + NSTAGE * STAGE_BYTES) cst = sbase;
    }

    // ---- epilogue ----
    const int qrow = lane >> 2;            // 0..7
    const int qcol = (lane & 3) * 2;       // 0,2,4,6

    if (dotOut == nullptr) {
        // GEMM1 path: K2 tail + bias + relu, store fp16
        #pragma unroll
        for (int mt = 0; mt < 4; mt++) {
            const int rowA = m0 + warp_m * 64 + mt * 16 + qrow;
            const int rowB = rowA + 8;

            float a2A[12], a2B[12];
            for (int k = 0; k < K2; k++) {
                a2A[k] = __ldg(A2 + (size_t)rowA * K2 + k);
                a2B[k] = __ldg(A2 + (size_t)rowB * K2 + k);
            }

            #pragma unroll
            for (int nt = 0; nt < 4; nt++) {
                const int colg = n0 + warp_n * 32 + nt * 8 + qcol;
                const float b0 = __ldg(bias + colg), b1 = __ldg(bias + colg + 1);
                float v0 = c[mt][nt][0] + b0, v1 = c[mt][nt][1] + b1;
                float v2 = c[mt][nt][2] + b0, v3 = c[mt][nt][3] + b1;

                for (int k = 0; k < K2; k++) {
                    const float w0 = __ldg(Wtail + (size_t)k * FD + colg);
                    const float w1 = __ldg(Wtail + (size_t)k * FD + colg + 1);
                    v0 += a2A[k] * w0; v1 += a2A[k] * w1;
                    v2 += a2B[k] * w0; v3 += a2B[k] * w1;
                }
                v0 = fmaxf(v0, 0.0f); v1 = fmaxf(v1, 0.0f);
                v2 = fmaxf(v2, 0.0f); v3 = fmaxf(v3, 0.0f);

                *(__half2*)(outH + (size_t)rowA * FD + colg) =
                    __halves2half2(__float2half_rn(v0), __float2half_rn(v1));
                *(__half2*)(outH + (size_t)rowB * FD + colg) =
                    __halves2half2(__float2half_rn(v2), __float2half_rn(v3));
            }
        }
    } else {
        // GEMM2 path: residual(A) + bias + relu, fused dot with w2 -> atomicAdd
        #pragma unroll
        for (int mt = 0; mt < 4; mt++) {
            const int rowA = m0 + warp_m * 64 + mt * 16 + qrow;
            const int rowB = rowA + 8;
            float sA = 0.0f, sB = 0.0f;

            #pragma unroll
            for (int nt = 0; nt < 4; nt++) {
                const int colg = n0 + warp_n * 32 + nt * 8 + qcol;
                const float b0 = __ldg(bias + colg), b1 = __ldg(bias + colg + 1);
                float v0 = c[mt][nt][0] + b0, v1 = c[mt][nt][1] + b1;
                float v2 = c[mt][nt][2] + b0, v3 = c[mt][nt][3] + b1;

                float2 hA = __half22float2(*(const __half2*)(A + (size_t)rowA * FD + colg));
                float2 hB = __half22float2(*(const __half2*)(A + (size_t)rowB * FD + colg));
                v0 += hA.x; v1 += hA.y;
                v2 += hB.x; v3 += hB.y;

                v0 = fmaxf(v0, 0.0f); v1 = fmaxf(v1, 0.0f);
                v2 = fmaxf(v2, 0.0f); v3 = fmaxf(v3, 0.0f);

                const float w0 = __ldg(w2 + colg), w1 = __ldg(w2 + colg + 1);
                sA += v0 * w0 + v1 * w1;
                sB += v2 * w0 + v3 * w1;
            }
            sA += __shfl_xor_sync(0xFFFFFFFFu, sA, 1);
            sA += __shfl_xor_sync(0xFFFFFFFFu, sA, 2);
            sB += __shfl_xor_sync(0xFFFFFFFFu, sB, 1);
            sB += __shfl_xor_sync(0xFFFFFFFFu, sB, 2);
            if ((lane & 3) == 0) {
                atomicAdd(dotOut + rowA, sA);
                atomicAdd(dotOut + rowB, sB);
            }
        }
    }
}

// ---------------------------------------------------------------------------
// Host orchestration
// ---------------------------------------------------------------------------
extern "C" void kernel_launch(void* const* d_in, const int* in_sizes, int n_in,
                              void* d_out, int out_size)
{
    const float* latent = (const float*)d_in[0];
    const float* rp     = (const float*)d_in[1];
    const float* w1[3] = {(const float*)d_in[2],  (const float*)d_in[8],  (const float*)d_in[14]};
    const float* b1[3] = {(const float*)d_in[3],  (const float*)d_in[9],  (const float*)d_in[15]};
    const float* wr[3] = {(const float*)d_in[4],  (const float*)d_in[10], (const float*)d_in[16]};
    const float* br[3] = {(const float*)d_in[5],  (const float*)d_in[11], (const float*)d_in[17]};
    const float* w2[3] = {(const float*)d_in[6],  (const float*)d_in[12], (const float*)d_in[18]};
    const float* b2[3] = {(const float*)d_in[7],  (const float*)d_in[13], (const float*)d_in[19]};

    float *feat, *std1, *std2;
    __half *lat, *h, *w1T_hi, *w1T_lo, *wrT_hi, *wrT_lo;
    cudaGetSymbolAddress((void**)&feat,   g_feat);
    cudaGetSymbolAddress((void**)&lat,    g_lat);
    cudaGetSymbolAddress((void**)&h,      g_h);
    cudaGetSymbolAddress((void**)&std1,   g_std1);
    cudaGetSymbolAddress((void**)&std2,   g_std2);
    cudaGetSymbolAddress((void**)&w1T_hi, g_w1T_hi);
    cudaGetSymbolAddress((void**)&w1T_lo, g_w1T_lo);
    cudaGetSymbolAddress((void**)&wrT_hi, g_wrT_hi);
    cudaGetSymbolAddress((void**)&wrT_lo, g_wrT_lo);

    float* out = (float*)d_out;

    cudaFuncSetAttribute(gemm_mma_kernel, cudaFuncAttributeMaxDynamicSharedMemorySize, SMEM_TOTAL);

    const dim3 ggrid(FD / BN, MROWS / BM);   // (4, 256)
    const dim3 tgrid(16, 16);

    conv_h_kernel<<<2048, 256>>>(latent, lat, MROWS * FD / 4);
    knn_feat_kernel<<<dim3(NPTS / 256, BATCH), 256>>>(rp, feat);

    const float* stdprev[3] = {nullptr, std1, std2};
    const float* a2s[3]     = {feat, std1, std2};
    const int    k2s[3]     = {12, 1, 1};
    float*       stdout_[3] = {std1, std2, out};

    for (int s = 0; s < 3; s++) {
        transW_kernel<<<tgrid, 256>>>(w1[s], w1T_hi, w1T_lo);
        gemm_mma_kernel<<<ggrid, 256, SMEM_TOTAL>>>(
            lat, w1T_hi, w1T_lo, b1[s],
            a2s[s], k2s[s], w1[s] + (size_t)FD * FD,
            h, nullptr, nullptr);
        transW_kernel<<<tgrid, 256>>>(wr[s], wrT_hi, wrT_lo);
        init_out_kernel<<<MROWS / 256, 256>>>(stdprev[s], b2[s], stdout_[s]);
        gemm_mma_kernel<<<ggrid, 256, SMEM_TOTAL>>>(
            h, wrT_hi, wrT_lo, br[s],
            nullptr, 0, nullptr,
            nullptr, w2[s], stdout_[s]);
    }
}

// round 9
// speedup vs baseline: 3.3769x; 1.4157x over previous
#include <cuda_runtime.h>
#include <cuda_fp16.h>
#include <cstdint>

#define BATCH 8
#define NPTS  4096
#define MROWS 32768
#define FD    512

// GEMM tiling
#define BM 128
#define BN 128
#define BK 32
#define ROWB 64                         // bytes per smem row (32 halves, no pad)
#define ARR_BYTES (BM * ROWB)           // 8192
#define STAGE_BYTES (2 * ARR_BYTES)     // 16384 (A, B)
#define NSTAGE 4
#define SMEM_TOTAL (NSTAGE * STAGE_BYTES)  // 65536

// ---------------------------------------------------------------------------
// Device scratch
// ---------------------------------------------------------------------------
__device__ float  g_feat[MROWS * 12];
__device__ __half g_lat[MROWS * FD];
__device__ __half g_h[MROWS * FD];
__device__ float  g_std1[MROWS];
__device__ float  g_std2[MROWS];
__device__ __half g_w1T[FD * FD];
__device__ __half g_wrT[FD * FD];

// ---------------------------------------------------------------------------
// Helpers
// ---------------------------------------------------------------------------
__device__ __forceinline__ uint32_t smem_u32(const void* p) {
    uint32_t a;
    asm("{ .reg .u64 t; cvta.to.shared.u64 t, %1; cvt.u32.u64 %0, t; }" : "=r"(a) : "l"(p));
    return a;
}

__device__ __forceinline__ void cp16(uint32_t s, const void* g) {
    asm volatile("cp.async.cg.shared.global [%0], [%1], 16;" :: "r"(s), "l"(g));
}
__device__ __forceinline__ void cp_commit() { asm volatile("cp.async.commit_group;"); }
template <int N>
__device__ __forceinline__ void cp_wait() { asm volatile("cp.async.wait_group %0;" :: "n"(N)); }

__device__ __forceinline__ void ldmx4(uint32_t addr, uint32_t& r0, uint32_t& r1, uint32_t& r2, uint32_t& r3) {
    asm volatile("ldmatrix.sync.aligned.m8n8.x4.shared.b16 {%0,%1,%2,%3}, [%4];"
        : "=r"(r0), "=r"(r1), "=r"(r2), "=r"(r3) : "r"(addr));
}

__device__ __forceinline__ void mma_f16(float* c, const uint32_t* a, const uint32_t* b) {
    asm volatile(
        "mma.sync.aligned.m16n8k16.row.col.f32.f16.f16.f32 "
        "{%0,%1,%2,%3}, {%4,%5,%6,%7}, {%8,%9}, {%0,%1,%2,%3};"
        : "+f"(c[0]), "+f"(c[1]), "+f"(c[2]), "+f"(c[3])
        : "r"(a[0]), "r"(a[1]), "r"(a[2]), "r"(a[3]), "r"(b[0]), "r"(b[1]));
}

// ---------------------------------------------------------------------------
// kNN + local covariance
// ---------------------------------------------------------------------------
__global__ __launch_bounds__(256) void knn_feat_kernel(
    const float* __restrict__ rp, float* __restrict__ feat)
{
    __shared__ float px[NPTS], py[NPTS], pz[NPTS];
    const int b = blockIdx.y;
    const float* base = rp + b * 3 * NPTS;
    for (int i = threadIdx.x; i < NPTS; i += 256) {
        px[i] = base[i]; py[i] = base[NPTS + i]; pz[i] = base[2 * NPTS + i];
    }
    __syncthreads();

    const int n = blockIdx.x * 256 + threadIdx.x;
    const float xi = px[n], yi = py[n], zi = pz[n];
    const float xxi = xi * xi + yi * yi + zi * zi;

    float bestv = -1e30f; int bestj = 0;
    for (int j = 0; j < NPTS; j++) {
        const float xj = px[j], yj = py[j], zj = pz[j];
        const float d = 2.0f * (xi * xj + yi * yj + zi * zj) - xxi - (xj * xj + yj * yj + zj * zj);
        if (j != n && d > bestv) { bestv = d; bestj = j; }
    }
    const float nx = px[bestj], ny = py[bestj], nz = pz[bestj];
    float* f = feat + (size_t)(b * NPTS + n) * 12;
    f[0] = xi;      f[1] = yi;      f[2] = zi;
    f[3] = xi * nx; f[4] = xi * ny; f[5] = xi * nz;
    f[6] = yi * nx; f[7] = yi * ny; f[8] = yi * nz;
    f[9] = zi * nx; f[10] = zi * ny; f[11] = zi * nz;
}

// ---------------------------------------------------------------------------
// fp32 -> fp16 convert (bulk, activations)
// ---------------------------------------------------------------------------
__global__ __launch_bounds__(256) void conv_h_kernel(
    const float* __restrict__ x, __half* __restrict__ o, int n4)
{
    for (int i = blockIdx.x * 256 + threadIdx.x; i < n4; i += gridDim.x * 256) {
        float4 v = ((const float4*)x)[i];
        __half2* p = (__half2*)o + i * 2;
        p[0] = __halves2half2(__float2half_rn(v.x), __float2half_rn(v.y));
        p[1] = __halves2half2(__float2half_rn(v.z), __float2half_rn(v.w));
    }
}

// ---------------------------------------------------------------------------
// W[512,512] (k-major) -> WT[n][k] fp16
// ---------------------------------------------------------------------------
__global__ __launch_bounds__(256) void transW_kernel(
    const float* __restrict__ W, __half* __restrict__ th)
{
    __shared__ float t[32][33];
    const int n0 = blockIdx.x * 32, k0 = blockIdx.y * 32;
    const int tx = threadIdx.x & 31, ty = threadIdx.x >> 5;
    #pragma unroll
    for (int i = 0; i < 4; i++)
        t[ty + i * 8][tx] = W[(size_t)(k0 + ty + i * 8) * FD + n0 + tx];
    __syncthreads();
    #pragma unroll
    for (int i = 0; i < 4; i++) {
        size_t o = (size_t)(n0 + ty + i * 8) * FD + k0 + tx;
        th[o] = __float2half_rn(t[tx][ty + i * 8]);
    }
}

// ---------------------------------------------------------------------------
// out[row] = (prev ? prev[row] : 0) + b2[0]   (pre-init for fused dot atomics)
// ---------------------------------------------------------------------------
__global__ __launch_bounds__(256) void init_out_kernel(
    const float* __restrict__ prev, const float* __restrict__ b2, float* __restrict__ out)
{
    const int i = blockIdx.x * 256 + threadIdx.x;
    out[i] = (prev ? prev[i] : 0.0f) + b2[0];
}

// ---------------------------------------------------------------------------
// fp16 mma.sync GEMM: C = A @ B^T, fp32 accum.
// 4-stage cp.async pipeline, swizzled smem, one barrier per K-chunk.
//  Mode 1 (dotOut == nullptr):  H = relu(C + A2@Wtail + bias) -> outH (fp16)
//  Mode 2 (dotOut != nullptr):  v = relu(C + A + bias); atomicAdd(dotOut, v@w2)
// ---------------------------------------------------------------------------
__global__ __launch_bounds__(256, 2) void gemm_mma_kernel(
    const __half* __restrict__ A,
    const __half* __restrict__ B,
    const float* __restrict__ bias,
    const float* __restrict__ A2, const int K2, const float* __restrict__ Wtail,
    __half* __restrict__ outH,
    const float* __restrict__ w2, float* __restrict__ dotOut)
{
    extern __shared__ __align__(16) char dsm[];
    const uint32_t sbase = smem_u32(dsm);

    const int tid = threadIdx.x;
    const int m0 = blockIdx.y * BM;
    const int n0 = blockIdx.x * BN;
    const int warp = tid >> 5, lane = tid & 31;
    const int warp_m = warp >> 2;          // 0..1 -> 64 rows
    const int warp_n = warp & 3;           // 0..3 -> 32 cols

    // ---- loader geometry (swizzled, 64B rows, 16B atoms) ----
    const int lr0 = tid >> 2;              // rows lr0 and lr0+64
    const int lkq = tid & 3;               // atom (8 halves)
    const uint32_t so0 = (uint32_t)(lr0 * ROWB + ((lkq ^ ((lr0 >> 1) & 3)) << 4));
    const uint32_t so1 = so0 + 64 * ROWB;  // 4096

    const __half* pA = A + (size_t)(m0 + lr0) * FD + lkq * 8;
    const __half* pB = B + (size_t)(n0 + lr0) * FD + lkq * 8;

    auto issue = [&](uint32_t st) {
        cp16(st + 0 * ARR_BYTES + so0, pA);
        cp16(st + 0 * ARR_BYTES + so1, pA + (size_t)64 * FD);
        cp16(st + 1 * ARR_BYTES + so0, pB);
        cp16(st + 1 * ARR_BYTES + so1, pB + (size_t)64 * FD);
        cp_commit();
        pA += BK; pB += BK;
    };

    // ---- fragment read offsets (loop-invariant; kk handled by ^32) ----
    const int arow = lane & 15;
    const int hi16 = lane >> 4;
    uint32_t aoff[4], boff[2];
    #pragma unroll
    for (int mt = 0; mt < 4; mt++) {
        const int r = warp_m * 64 + mt * 16 + arow;
        aoff[mt] = (uint32_t)(r * ROWB + ((hi16 ^ ((r >> 1) & 3)) << 4));
    }
    #pragma unroll
    for (int pr = 0; pr < 2; pr++) {
        const int r = warp_n * 32 + pr * 16 + arow;
        boff[pr] = (uint32_t)(r * ROWB + ((hi16 ^ ((r >> 1) & 3)) << 4));
    }

    float c[4][4][4];
    #pragma unroll
    for (int i = 0; i < 4; i++)
        #pragma unroll
        for (int j = 0; j < 4; j++)
            #pragma unroll
            for (int q = 0; q < 4; q++) c[i][j][q] = 0.0f;

    auto compute = [&](uint32_t st) {
        #pragma unroll
        for (int kk = 0; kk < 2; kk++) {
            const uint32_t kx = (uint32_t)(kk << 5);
            uint32_t a[4][4], bf[4][2];
            #pragma unroll
            for (int mt = 0; mt < 4; mt++) {
                const uint32_t ad = st + (aoff[mt] ^ kx);
                ldmx4(ad + 0 * ARR_BYTES, a[mt][0], a[mt][1], a[mt][2], a[mt][3]);
            }
            #pragma unroll
            for (int pr = 0; pr < 2; pr++) {
                const uint32_t bd = st + (boff[pr] ^ kx);
                uint32_t r0, r1, r2, r3;
                ldmx4(bd + 1 * ARR_BYTES, r0, r1, r2, r3);
                bf[2*pr][0] = r0; bf[2*pr][1] = r2; bf[2*pr+1][0] = r1; bf[2*pr+1][1] = r3;
            }
            #pragma unroll
            for (int mt = 0; mt < 4; mt++)
                #pragma unroll
                for (int nt = 0; nt < 4; nt++)
                    mma_f16(c[mt][nt], a[mt], bf[nt]);
        }
    };

    // ---- 4-stage pipelined mainloop, one barrier per chunk ----
    issue(sbase + 0 * STAGE_BYTES);
    issue(sbase + 1 * STAGE_BYTES);
    issue(sbase + 2 * STAGE_BYTES);

    uint32_t cst = sbase;                   // compute stage for chunk ch
    uint32_t ist = sbase + 3 * STAGE_BYTES; // issue stage for chunk ch+3

    #pragma unroll 1
    for (int ch = 0; ch < FD / BK; ch++) {
        cp_wait<2>();
        __syncthreads();
        if (ch + 3 < FD / BK) {
            issue(ist);
            ist += STAGE_BYTES;
            if (ist == sbase + NSTAGE * STAGE_BYTES) ist = sbase;
        }
        compute(cst);
        cst += STAGE_BYTES;
        if (cst == sbase + NSTAGE * STAGE_BYTES) cst = sbase;
    }

    // ---- epilogue ----
    const int qrow = lane >> 2;            // 0..7
    const int qcol = (lane & 3) * 2;       // 0,2,4,6

    if (dotOut == nullptr) {
        // GEMM1 path: K2 tail + bias + relu, store fp16
        #pragma unroll
        for (int mt = 0; mt < 4; mt++) {
            const int rowA = m0 + warp_m * 64 + mt * 16 + qrow;
            const int rowB = rowA + 8;

            float a2A[12], a2B[12];
            for (int k = 0; k < K2; k++) {
                a2A[k] = __ldg(A2 + (size_t)rowA * K2 + k);
                a2B[k] = __ldg(A2 + (size_t)rowB * K2 + k);
            }

            #pragma unroll
            for (int nt = 0; nt < 4; nt++) {
                const int colg = n0 + warp_n * 32 + nt * 8 + qcol;
                const float b0 = __ldg(bias + colg), b1 = __ldg(bias + colg + 1);
                float v0 = c[mt][nt][0] + b0, v1 = c[mt][nt][1] + b1;
                float v2 = c[mt][nt][2] + b0, v3 = c[mt][nt][3] + b1;

                for (int k = 0; k < K2; k++) {
                    const float w0 = __ldg(Wtail + (size_t)k * FD + colg);
                    const float w1 = __ldg(Wtail + (size_t)k * FD + colg + 1);
                    v0 += a2A[k] * w0; v1 += a2A[k] * w1;
                    v2 += a2B[k] * w0; v3 += a2B[k] * w1;
                }
                v0 = fmaxf(v0, 0.0f); v1 = fmaxf(v1, 0.0f);
                v2 = fmaxf(v2, 0.0f); v3 = fmaxf(v3, 0.0f);

                *(__half2*)(outH + (size_t)rowA * FD + colg) =
                    __halves2half2(__float2half_rn(v0), __float2half_rn(v1));
                *(__half2*)(outH + (size_t)rowB * FD + colg) =
                    __halves2half2(__float2half_rn(v2), __float2half_rn(v3));
            }
        }
    } else {
        // GEMM2 path: residual(A) + bias + relu, fused dot with w2 -> atomicAdd
        #pragma unroll
        for (int mt = 0; mt < 4; mt++) {
            const int rowA = m0 + warp_m * 64 + mt * 16 + qrow;
            const int rowB = rowA + 8;
            float sA = 0.0f, sB = 0.0f;

            #pragma unroll
            for (int nt = 0; nt < 4; nt++) {
                const int colg = n0 + warp_n * 32 + nt * 8 + qcol;
                const float b0 = __ldg(bias + colg), b1 = __ldg(bias + colg + 1);
                float v0 = c[mt][nt][0] + b0, v1 = c[mt][nt][1] + b1;
                float v2 = c[mt][nt][2] + b0, v3 = c[mt][nt][3] + b1;

                float2 hA = __half22float2(*(const __half2*)(A + (size_t)rowA * FD + colg));
                float2 hB = __half22float2(*(const __half2*)(A + (size_t)rowB * FD + colg));
                v0 += hA.x; v1 += hA.y;
                v2 += hB.x; v3 += hB.y;

                v0 = fmaxf(v0, 0.0f); v1 = fmaxf(v1, 0.0f);
                v2 = fmaxf(v2, 0.0f); v3 = fmaxf(v3, 0.0f);

                const float w0 = __ldg(w2 + colg), w1 = __ldg(w2 + colg + 1);
                sA += v0 * w0 + v1 * w1;
                sB += v2 * w0 + v3 * w1;
            }
            sA += __shfl_xor_sync(0xFFFFFFFFu, sA, 1);
            sA += __shfl_xor_sync(0xFFFFFFFFu, sA, 2);
            sB += __shfl_xor_sync(0xFFFFFFFFu, sB, 1);
            sB += __shfl_xor_sync(0xFFFFFFFFu, sB, 2);
            if ((lane & 3) == 0) {
                atomicAdd(dotOut + rowA, sA);
                atomicAdd(dotOut + rowB, sB);
            }
        }
    }
}

// ---------------------------------------------------------------------------
// Host orchestration
// ---------------------------------------------------------------------------
extern "C" void kernel_launch(void* const* d_in, const int* in_sizes, int n_in,
                              void* d_out, int out_size)
{
    const float* latent = (const float*)d_in[0];
    const float* rp     = (const float*)d_in[1];
    const float* w1[3] = {(const float*)d_in[2],  (const float*)d_in[8],  (const float*)d_in[14]};
    const float* b1[3] = {(const float*)d_in[3],  (const float*)d_in[9],  (const float*)d_in[15]};
    const float* wr[3] = {(const float*)d_in[4],  (const float*)d_in[10], (const float*)d_in[16]};
    const float* br[3] = {(const float*)d_in[5],  (const float*)d_in[11], (const float*)d_in[17]};
    const float* w2[3] = {(const float*)d_in[6],  (const float*)d_in[12], (const float*)d_in[18]};
    const float* b2[3] = {(const float*)d_in[7],  (const float*)d_in[13], (const float*)d_in[19]};

    float *feat, *std1, *std2;
    __half *lat, *h, *w1T, *wrT;
    cudaGetSymbolAddress((void**)&feat, g_feat);
    cudaGetSymbolAddress((void**)&lat,  g_lat);
    cudaGetSymbolAddress((void**)&h,    g_h);
    cudaGetSymbolAddress((void**)&std1, g_std1);
    cudaGetSymbolAddress((void**)&std2, g_std2);
    cudaGetSymbolAddress((void**)&w1T,  g_w1T);
    cudaGetSymbolAddress((void**)&wrT,  g_wrT);

    float* out = (float*)d_out;

    cudaFuncSetAttribute(gemm_mma_kernel, cudaFuncAttributeMaxDynamicSharedMemorySize, SMEM_TOTAL);

    const dim3 ggrid(FD / BN, MROWS / BM);   // (4, 256)
    const dim3 tgrid(16, 16);

    conv_h_kernel<<<2048, 256>>>(latent, lat, MROWS * FD / 4);
    knn_feat_kernel<<<dim3(NPTS / 256, BATCH), 256>>>(rp, feat);

    const float* stdprev[3] = {nullptr, std1, std2};
    const float* a2s[3]     = {feat, std1, std2};
    const int    k2s[3]     = {12, 1, 1};
    float*       stdout_[3] = {std1, std2, out};

    for (int s = 0; s < 3; s++) {
        transW_kernel<<<tgrid, 256>>>(w1[s], w1T);
        gemm_mma_kernel<<<ggrid, 256, SMEM_TOTAL>>>(
            lat, w1T, b1[s],
            a2s[s], k2s[s], w1[s] + (size_t)FD * FD,
            h, nullptr, nullptr);
        transW_kernel<<<tgrid, 256>>>(wr[s], wrT);
        init_out_kernel<<<MROWS / 256, 256>>>(stdprev[s], b2[s], stdout_[s]);
        gemm_mma_kernel<<<ggrid, 256, SMEM_TOTAL>>>(
            h, wrT, br[s],
            nullptr, 0, nullptr,
            nullptr, w2[s], stdout_[s]);
    }
}

// round 10
// speedup vs baseline: 3.6012x; 1.0664x over previous
#include <cuda_runtime.h>
#include <cuda_fp16.h>
#include <cstdint>

#define BATCH 8
#define NPTS  4096
#define MROWS 32768
#define FD    512

// GEMM tiling
#define BM 128
#define BN 128
#define BK 64
#define ROWB 128                        // bytes per smem row (64 halves)
#define ARR_BYTES (BM * ROWB)           // 16384
#define STAGE_BYTES (2 * ARR_BYTES)     // 32768 (A, B)
#define NSTAGE 3
#define SMEM_TOTAL (NSTAGE * STAGE_BYTES)  // 98304

// ---------------------------------------------------------------------------
// Device scratch
// ---------------------------------------------------------------------------
__device__ float  g_feat[MROWS * 12];
__device__ __half g_lat[MROWS * FD];
__device__ __half g_h[MROWS * FD];
__device__ float  g_std1[MROWS];
__device__ float  g_std2[MROWS];
__device__ __half g_w1T[FD * FD];
__device__ __half g_wrT[FD * FD];

// ---------------------------------------------------------------------------
// Helpers
// ---------------------------------------------------------------------------
__device__ __forceinline__ uint32_t smem_u32(const void* p) {
    uint32_t a;
    asm("{ .reg .u64 t; cvta.to.shared.u64 t, %1; cvt.u32.u64 %0, t; }" : "=r"(a) : "l"(p));
    return a;
}

__device__ __forceinline__ void cp16(uint32_t s, const void* g) {
    asm volatile("cp.async.cg.shared.global [%0], [%1], 16;" :: "r"(s), "l"(g));
}
__device__ __forceinline__ void cp_commit() { asm volatile("cp.async.commit_group;"); }
template <int N>
__device__ __forceinline__ void cp_wait() { asm volatile("cp.async.wait_group %0;" :: "n"(N)); }

__device__ __forceinline__ void ldmx4(uint32_t addr, uint32_t& r0, uint32_t& r1, uint32_t& r2, uint32_t& r3) {
    asm volatile("ldmatrix.sync.aligned.m8n8.x4.shared.b16 {%0,%1,%2,%3}, [%4];"
        : "=r"(r0), "=r"(r1), "=r"(r2), "=r"(r3) : "r"(addr));
}

__device__ __forceinline__ void mma_f16(float* c, const uint32_t* a, const uint32_t* b) {
    asm volatile(
        "mma.sync.aligned.m16n8k16.row.col.f32.f16.f16.f32 "
        "{%0,%1,%2,%3}, {%4,%5,%6,%7}, {%8,%9}, {%0,%1,%2,%3};"
        : "+f"(c[0]), "+f"(c[1]), "+f"(c[2]), "+f"(c[3])
        : "r"(a[0]), "r"(a[1]), "r"(a[2]), "r"(a[3]), "r"(b[0]), "r"(b[1]));
}

// ---------------------------------------------------------------------------
// kNN + local covariance
// ---------------------------------------------------------------------------
__global__ __launch_bounds__(256) void knn_feat_kernel(
    const float* __restrict__ rp, float* __restrict__ feat)
{
    __shared__ float px[NPTS], py[NPTS], pz[NPTS];
    const int b = blockIdx.y;
    const float* base = rp + b * 3 * NPTS;
    for (int i = threadIdx.x; i < NPTS; i += 256) {
        px[i] = base[i]; py[i] = base[NPTS + i]; pz[i] = base[2 * NPTS + i];
    }
    __syncthreads();

    const int n = blockIdx.x * 256 + threadIdx.x;
    const float xi = px[n], yi = py[n], zi = pz[n];
    const float xxi = xi * xi + yi * yi + zi * zi;

    float bestv = -1e30f; int bestj = 0;
    for (int j = 0; j < NPTS; j++) {
        const float xj = px[j], yj = py[j], zj = pz[j];
        const float d = 2.0f * (xi * xj + yi * yj + zi * zj) - xxi - (xj * xj + yj * yj + zj * zj);
        if (j != n && d > bestv) { bestv = d; bestj = j; }
    }
    const float nx = px[bestj], ny = py[bestj], nz = pz[bestj];
    float* f = feat + (size_t)(b * NPTS + n) * 12;
    f[0] = xi;      f[1] = yi;      f[2] = zi;
    f[3] = xi * nx; f[4] = xi * ny; f[5] = xi * nz;
    f[6] = yi * nx; f[7] = yi * ny; f[8] = yi * nz;
    f[9] = zi * nx; f[10] = zi * ny; f[11] = zi * nz;
}

// ---------------------------------------------------------------------------
// fp32 -> fp16 convert (bulk, activations)
// ---------------------------------------------------------------------------
__global__ __launch_bounds__(256) void conv_h_kernel(
    const float* __restrict__ x, __half* __restrict__ o, int n4)
{
    for (int i = blockIdx.x * 256 + threadIdx.x; i < n4; i += gridDim.x * 256) {
        float4 v = ((const float4*)x)[i];
        __half2* p = (__half2*)o + i * 2;
        p[0] = __halves2half2(__float2half_rn(v.x), __float2half_rn(v.y));
        p[1] = __halves2half2(__float2half_rn(v.z), __float2half_rn(v.w));
    }
}

// ---------------------------------------------------------------------------
// W[512,512] (k-major) -> WT[n][k] fp16
// ---------------------------------------------------------------------------
__global__ __launch_bounds__(256) void transW_kernel(
    const float* __restrict__ W, __half* __restrict__ th)
{
    __shared__ float t[32][33];
    const int n0 = blockIdx.x * 32, k0 = blockIdx.y * 32;
    const int tx = threadIdx.x & 31, ty = threadIdx.x >> 5;
    #pragma unroll
    for (int i = 0; i < 4; i++)
        t[ty + i * 8][tx] = W[(size_t)(k0 + ty + i * 8) * FD + n0 + tx];
    __syncthreads();
    #pragma unroll
    for (int i = 0; i < 4; i++) {
        size_t o = (size_t)(n0 + ty + i * 8) * FD + k0 + tx;
        th[o] = __float2half_rn(t[tx][ty + i * 8]);
    }
}

// ---------------------------------------------------------------------------
// out[row] = (prev ? prev[row] : 0) + b2[0]   (pre-init for fused dot atomics)
// ---------------------------------------------------------------------------
__global__ __launch_bounds__(256) void init_out_kernel(
    const float* __restrict__ prev, const float* __restrict__ b2, float* __restrict__ out)
{
    const int i = blockIdx.x * 256 + threadIdx.x;
    out[i] = (prev ? prev[i] : 0.0f) + b2[0];
}

// ---------------------------------------------------------------------------
// fp16 mma.sync GEMM: C = A @ B^T, fp32 accum. BK=64 chunks, 3-stage
// cp.async pipeline, SW128 swizzle (atom ^ row&7), one barrier per chunk.
//  MODE 0:  H = relu(C + A2@Wtail + bias) -> outH (fp16)
//  MODE 1:  v = relu(C + A + bias); atomicAdd(dotOut, v@w2)
// ---------------------------------------------------------------------------
template <int MODE>
__global__ __launch_bounds__(256, 2) void gemm_mma_kernel(
    const __half* __restrict__ A,
    const __half* __restrict__ B,
    const float* __restrict__ bias,
    const float* __restrict__ A2, const int K2, const float* __restrict__ Wtail,
    __half* __restrict__ outH,
    const float* __restrict__ w2, float* __restrict__ dotOut)
{
    extern __shared__ __align__(16) char dsm[];
    const uint32_t sbase = smem_u32(dsm);

    const int tid = threadIdx.x;
    const int m0 = blockIdx.y * BM;
    const int n0 = blockIdx.x * BN;
    const int warp = tid >> 5, lane = tid & 31;
    const int warp_m = warp >> 2;          // 0..1 -> 64 rows
    const int warp_n = warp & 3;           // 0..3 -> 32 cols

    // ---- loader geometry: 8 lanes per 128B row, 4 row-groups of 32 ----
    const int lr   = tid >> 3;             // 0..31 (rows lr, lr+32, lr+64, lr+96)
    const int atom = tid & 7;              // 16B atom within row
    const uint32_t so0 = (uint32_t)(lr * ROWB + ((atom ^ (lr & 7)) << 4));

    const __half* pA = A + (size_t)(m0 + lr) * FD + atom * 8;
    const __half* pB = B + (size_t)(n0 + lr) * FD + atom * 8;

    auto issue = [&](uint32_t st) {
        #pragma unroll
        for (int i = 0; i < 4; i++) {
            cp16(st + 0 * ARR_BYTES + so0 + i * (32 * ROWB), pA + (size_t)(32 * i) * FD);
            cp16(st + 1 * ARR_BYTES + so0 + i * (32 * ROWB), pB + (size_t)(32 * i) * FD);
        }
        cp_commit();
        pA += BK; pB += BK;
    };

    // ---- fragment read offsets (loop-invariant; kk handled by ^(kk<<5)) ----
    const int arow = lane & 15;
    const int hi16 = lane >> 4;
    uint32_t aoff[4], boff[2];
    #pragma unroll
    for (int mt = 0; mt < 4; mt++) {
        const int r = warp_m * 64 + mt * 16 + arow;
        aoff[mt] = (uint32_t)(r * ROWB + ((hi16 ^ (r & 7)) << 4));
    }
    #pragma unroll
    for (int pr = 0; pr < 2; pr++) {
        const int r = warp_n * 32 + pr * 16 + arow;
        boff[pr] = (uint32_t)(r * ROWB + ((hi16 ^ (r & 7)) << 4));
    }

    float c[4][4][4];
    #pragma unroll
    for (int i = 0; i < 4; i++)
        #pragma unroll
        for (int j = 0; j < 4; j++)
            #pragma unroll
            for (int q = 0; q < 4; q++) c[i][j][q] = 0.0f;

    auto compute = [&](uint32_t st) {
        #pragma unroll
        for (int kk = 0; kk < 4; kk++) {
            const uint32_t kx = (uint32_t)(kk << 5);   // flips atom bits [2:1]
            uint32_t a[4][4], bf[4][2];
            #pragma unroll
            for (int mt = 0; mt < 4; mt++) {
                const uint32_t ad = st + (aoff[mt] ^ kx);
                ldmx4(ad + 0 * ARR_BYTES, a[mt][0], a[mt][1], a[mt][2], a[mt][3]);
            }
            #pragma unroll
            for (int pr = 0; pr < 2; pr++) {
                const uint32_t bd = st + (boff[pr] ^ kx);
                uint32_t r0, r1, r2, r3;
                ldmx4(bd + 1 * ARR_BYTES, r0, r1, r2, r3);
                bf[2*pr][0] = r0; bf[2*pr][1] = r2; bf[2*pr+1][0] = r1; bf[2*pr+1][1] = r3;
            }
            #pragma unroll
            for (int mt = 0; mt < 4; mt++)
                #pragma unroll
                for (int nt = 0; nt < 4; nt++)
                    mma_f16(c[mt][nt], a[mt], bf[nt]);
        }
    };

    // ---- 3-stage pipelined mainloop, one barrier per chunk ----
    issue(sbase + 0 * STAGE_BYTES);
    issue(sbase + 1 * STAGE_BYTES);

    uint32_t cst = sbase;                   // compute stage for chunk ch
    uint32_t ist = sbase + 2 * STAGE_BYTES; // issue stage for chunk ch+2

    #pragma unroll 1
    for (int ch = 0; ch < FD / BK; ch++) {
        cp_wait<1>();
        __syncthreads();
        if (ch + 2 < FD / BK) {
            issue(ist);
            ist += STAGE_BYTES;
            if (ist == sbase + NSTAGE * STAGE_BYTES) ist = sbase;
        }
        compute(cst);
        cst += STAGE_BYTES;
        if (cst == sbase + NSTAGE * STAGE_BYTES) cst = sbase;
    }

    // ---- epilogue ----
    const int qrow = lane >> 2;            // 0..7
    const int qcol = (lane & 3) * 2;       // 0,2,4,6

    if (MODE == 0) {
        // GEMM1 path: K2 tail + bias + relu, store fp16
        #pragma unroll
        for (int mt = 0; mt < 4; mt++) {
            const int rowA = m0 + warp_m * 64 + mt * 16 + qrow;
            const int rowB = rowA + 8;

            float a2A[12], a2B[12];
            for (int k = 0; k < K2; k++) {
                a2A[k] = __ldg(A2 + (size_t)rowA * K2 + k);
                a2B[k] = __ldg(A2 + (size_t)rowB * K2 + k);
            }

            #pragma unroll
            for (int nt = 0; nt < 4; nt++) {
                const int colg = n0 + warp_n * 32 + nt * 8 + qcol;
                const float b0 = __ldg(bias + colg), b1 = __ldg(bias + colg + 1);
                float v0 = c[mt][nt][0] + b0, v1 = c[mt][nt][1] + b1;
                float v2 = c[mt][nt][2] + b0, v3 = c[mt][nt][3] + b1;

                for (int k = 0; k < K2; k++) {
                    const float w0 = __ldg(Wtail + (size_t)k * FD + colg);
                    const float w1 = __ldg(Wtail + (size_t)k * FD + colg + 1);
                    v0 += a2A[k] * w0; v1 += a2A[k] * w1;
                    v2 += a2B[k] * w0; v3 += a2B[k] * w1;
                }
                v0 = fmaxf(v0, 0.0f); v1 = fmaxf(v1, 0.0f);
                v2 = fmaxf(v2, 0.0f); v3 = fmaxf(v3, 0.0f);

                *(__half2*)(outH + (size_t)rowA * FD + colg) =
                    __halves2half2(__float2half_rn(v0), __float2half_rn(v1));
                *(__half2*)(outH + (size_t)rowB * FD + colg) =
                    __halves2half2(__float2half_rn(v2), __float2half_rn(v3));
            }
        }
    } else {
        // GEMM2 path: residual(A) + bias + relu, fused dot with w2 -> atomicAdd
        #pragma unroll
        for (int mt = 0; mt < 4; mt++) {
            const int rowA = m0 + warp_m * 64 + mt * 16 + qrow;
            const int rowB = rowA + 8;
            float sA = 0.0f, sB = 0.0f;

            #pragma unroll
            for (int nt = 0; nt < 4; nt++) {
                const int colg = n0 + warp_n * 32 + nt * 8 + qcol;
                const float b0 = __ldg(bias + colg), b1 = __ldg(bias + colg + 1);
                float v0 = c[mt][nt][0] + b0, v1 = c[mt][nt][1] + b1;
                float v2 = c[mt][nt][2] + b0, v3 = c[mt][nt][3] + b1;

                float2 hA = __half22float2(*(const __half2*)(A + (size_t)rowA * FD + colg));
                float2 hB = __half22float2(*(const __half2*)(A + (size_t)rowB * FD + colg));
                v0 += hA.x; v1 += hA.y;
                v2 += hB.x; v3 += hB.y;

                v0 = fmaxf(v0, 0.0f); v1 = fmaxf(v1, 0.0f);
                v2 = fmaxf(v2, 0.0f); v3 = fmaxf(v3, 0.0f);

                const float w0 = __ldg(w2 + colg), w1 = __ldg(w2 + colg + 1);
                sA += v0 * w0 + v1 * w1;
                sB += v2 * w0 + v3 * w1;
            }
            sA += __shfl_xor_sync(0xFFFFFFFFu, sA, 1);
            sA += __shfl_xor_sync(0xFFFFFFFFu, sA, 2);
            sB += __shfl_xor_sync(0xFFFFFFFFu, sB, 1);
            sB += __shfl_xor_sync(0xFFFFFFFFu, sB, 2);
            if ((lane & 3) == 0) {
                atomicAdd(dotOut + rowA, sA);
                atomicAdd(dotOut + rowB, sB);
            }
        }
    }
}

// ---------------------------------------------------------------------------
// Host orchestration
// ---------------------------------------------------------------------------
extern "C" void kernel_launch(void* const* d_in, const int* in_sizes, int n_in,
                              void* d_out, int out_size)
{
    const float* latent = (const float*)d_in[0];
    const float* rp     = (const float*)d_in[1];
    const float* w1[3] = {(const float*)d_in[2],  (const float*)d_in[8],  (const float*)d_in[14]};
    const float* b1[3] = {(const float*)d_in[3],  (const float*)d_in[9],  (const float*)d_in[15]};
    const float* wr[3] = {(const float*)d_in[4],  (const float*)d_in[10], (const float*)d_in[16]};
    const float* br[3] = {(const float*)d_in[5],  (const float*)d_in[11], (const float*)d_in[17]};
    const float* w2[3] = {(const float*)d_in[6],  (const float*)d_in[12], (const float*)d_in[18]};
    const float* b2[3] = {(const float*)d_in[7],  (const float*)d_in[13], (const float*)d_in[19]};

    float *feat, *std1, *std2;
    __half *lat, *h, *w1T, *wrT;
    cudaGetSymbolAddress((void**)&feat, g_feat);
    cudaGetSymbolAddress((void**)&lat,  g_lat);
    cudaGetSymbolAddress((void**)&h,    g_h);
    cudaGetSymbolAddress((void**)&std1, g_std1);
    cudaGetSymbolAddress((void**)&std2, g_std2);
    cudaGetSymbolAddress((void**)&w1T,  g_w1T);
    cudaGetSymbolAddress((void**)&wrT,  g_wrT);

    float* out = (float*)d_out;

    cudaFuncSetAttribute(gemm_mma_kernel<0>, cudaFuncAttributeMaxDynamicSharedMemorySize, SMEM_TOTAL);
    cudaFuncSetAttribute(gemm_mma_kernel<1>, cudaFuncAttributeMaxDynamicSharedMemorySize, SMEM_TOTAL);

    const dim3 ggrid(FD / BN, MROWS / BM);   // (4, 256)
    const dim3 tgrid(16, 16);

    conv_h_kernel<<<2048, 256>>>(latent, lat, MROWS * FD / 4);
    knn_feat_kernel<<<dim3(NPTS / 256, BATCH), 256>>>(rp, feat);

    const float* stdprev[3] = {nullptr, std1, std2};
    const float* a2s[3]     = {feat, std1, std2};
    const int    k2s[3]     = {12, 1, 1};
    float*       stdout_[3] = {std1, std2, out};

    for (int s = 0; s < 3; s++) {
        transW_kernel<<<tgrid, 256>>>(w1[s], w1T);
        gemm_mma_kernel<0><<<ggrid, 256, SMEM_TOTAL>>>(
            lat, w1T, b1[s],
            a2s[s], k2s[s], w1[s] + (size_t)FD * FD,
            h, nullptr, nullptr);
        transW_kernel<<<tgrid, 256>>>(wr[s], wrT);
        init_out_kernel<<<MROWS / 256, 256>>>(stdprev[s], b2[s], stdout_[s]);
        gemm_mma_kernel<1><<<ggrid, 256, SMEM_TOTAL>>>(
            h, wrT, br[s],
            nullptr, 0, nullptr,
            nullptr, w2[s], stdout_[s]);
    }
}

// round 12
// speedup vs baseline: 3.7534x; 1.0423x over previous
#include <cuda_runtime.h>
#include <cuda_fp16.h>
#include <cstdint>

#define BATCH 8
#define NPTS  4096
#define MROWS 32768
#define FD    512

// GEMM tiling
#define BM 128
#define BN 128
#define BK 64
#define CHUNK_BYTES 16384               // one array (128 rows x 64 k x 2B)
#define STAGE_BYTES (2 * CHUNK_BYTES)   // A + B
#define NSTAGE 3
#define SMEM_TOTAL (NSTAGE * STAGE_BYTES)  // 98304
#define MBLK_STRIDE (8 * CHUNK_BYTES)   // 8 chunks per 128-row/col block

// ---------------------------------------------------------------------------
// Device scratch (fragment-layout fp16 operands)
// ---------------------------------------------------------------------------
__device__ float  g_feat[MROWS * 12];
__device__ __half g_lat[MROWS * FD];    // A-fragment layout
__device__ __half g_h[MROWS * FD];      // A-fragment layout (GEMM1 out / GEMM2 in)
__device__ float  g_std1[MROWS];
__device__ float  g_std2[MROWS];
__device__ __half g_w1T[FD * FD];       // B-fragment layout
__device__ __half g_wrT[FD * FD];       // B-fragment layout

// ---------------------------------------------------------------------------
// Helpers
// ---------------------------------------------------------------------------
__device__ __forceinline__ uint32_t smem_u32(const void* p) {
    uint32_t a;
    asm("{ .reg .u64 t; cvta.to.shared.u64 t, %1; cvt.u32.u64 %0, t; }" : "=r"(a) : "l"(p));
    return a;
}

__device__ __forceinline__ void bulk_cp(uint32_t dst, const void* src, uint32_t bytes, uint32_t mbar) {
    asm volatile(
        "cp.async.bulk.shared::cluster.global.mbarrier::complete_tx::bytes [%0], [%1], %2, [%3];"
        :: "r"(dst), "l"(src), "r"(bytes), "r"(mbar) : "memory");
}

#define MB_INIT(mb, c)    asm volatile("mbarrier.init.shared.b64 [%0], %1;" :: "r"(mb), "r"(c) : "memory")
#define MB_EXPECT(mb, tx) asm volatile("mbarrier.arrive.expect_tx.shared.b64 _, [%0], %1;" :: "r"(mb), "r"(tx) : "memory")

__device__ __forceinline__ void mb_wait_parity(uint32_t mb, uint32_t par) {
    uint32_t done;
    asm volatile(
        "{\n\t.reg .pred p;\n\tmbarrier.try_wait.parity.acquire.cta.shared::cta.b64 p, [%1], %2;\n\tselp.b32 %0, 1, 0, p;\n\t}"
        : "=r"(done) : "r"(mb), "r"(par) : "memory");
    if (!done) {
        asm volatile(
            "{\n\t.reg .pred P1;\n\tWL_%=:\n\t"
            "mbarrier.try_wait.parity.acquire.cta.shared::cta.b64 P1, [%0], %1, 0x989680;\n\t"
            "@P1 bra.uni WD_%=;\n\tbra.uni WL_%=;\n\tWD_%=:\n\t}"
            :: "r"(mb), "r"(par) : "memory");
    }
}

#define LDS128(r0, r1, r2, r3, addr) \
    asm volatile("ld.shared.v4.b32 {%0,%1,%2,%3}, [%4];" \
        : "=r"(r0), "=r"(r1), "=r"(r2), "=r"(r3) : "r"(addr))

__device__ __forceinline__ void mma_f16(float* c, const uint32_t* a, const uint32_t* b) {
    asm volatile(
        "mma.sync.aligned.m16n8k16.row.col.f32.f16.f16.f32 "
        "{%0,%1,%2,%3}, {%4,%5,%6,%7}, {%8,%9}, {%0,%1,%2,%3};"
        : "+f"(c[0]), "+f"(c[1]), "+f"(c[2]), "+f"(c[3])
        : "r"(a[0]), "r"(a[1]), "r"(a[2]), "r"(a[3]), "r"(b[0]), "r"(b[1]));
}

__device__ __forceinline__ uint32_t h2u(__half2 h) { return *(uint32_t*)&h; }

// ---------------------------------------------------------------------------
// kNN + local covariance
// ---------------------------------------------------------------------------
__global__ __launch_bounds__(256) void knn_feat_kernel(
    const float* __restrict__ rp, float* __restrict__ feat)
{
    __shared__ float px[NPTS], py[NPTS], pz[NPTS];
    const int b = blockIdx.y;
    const float* base = rp + b * 3 * NPTS;
    for (int i = threadIdx.x; i < NPTS; i += 256) {
        px[i] = base[i]; py[i] = base[NPTS + i]; pz[i] = base[2 * NPTS + i];
    }
    __syncthreads();

    const int n = blockIdx.x * 256 + threadIdx.x;
    const float xi = px[n], yi = py[n], zi = pz[n];
    const float xxi = xi * xi + yi * yi + zi * zi;

    float bestv = -1e30f; int bestj = 0;
    for (int j = 0; j < NPTS; j++) {
        const float xj = px[j], yj = py[j], zj = pz[j];
        const float d = 2.0f * (xi * xj + yi * yj + zi * zj) - xxi - (xj * xj + yj * yj + zj * zj);
        if (j != n && d > bestv) { bestv = d; bestj = j; }
    }
    const float nx = px[bestj], ny = py[bestj], nz = pz[bestj];
    float* f = feat + (size_t)(b * NPTS + n) * 12;
    f[0] = xi;      f[1] = yi;      f[2] = zi;
    f[3] = xi * nx; f[4] = xi * ny; f[5] = xi * nz;
    f[6] = yi * nx; f[7] = yi * ny; f[8] = yi * nz;
    f[9] = zi * nx; f[10] = zi * ny; f[11] = zi * nz;
}

// ---------------------------------------------------------------------------
// latent fp32 [m][k] -> A-fragment fp16 layout.
// Unit u (16B): lane=u&31, mtb=(u>>5)&7, kk=(u>>8)&3, kch=(u>>10)&7, mblk=u>>13
//   m = mblk*128 + mtb*16 + lane/4 ; k = kch*64 + kk*16 + (lane%4)*2
//   regs: a0=(m,k) a1=(m+8,k) a2=(m,k+8) a3=(m+8,k+8)
// ---------------------------------------------------------------------------
__global__ __launch_bounds__(256) void conv_frag_kernel(
    const float* __restrict__ x, __half* __restrict__ o)
{
    const int u = blockIdx.x * 256 + threadIdx.x;
    const int lane = u & 31, mtb = (u >> 5) & 7, kk = (u >> 8) & 3;
    const int kch = (u >> 10) & 7, mblk = u >> 13;
    const int m = mblk * 128 + mtb * 16 + (lane >> 2);
    const int k = kch * 64 + kk * 16 + (lane & 3) * 2;
    const float* s0 = x + (size_t)m * FD + k;
    const float* s1 = s0 + 8 * FD;
    float2 f00 = *(const float2*)(s0);
    float2 f10 = *(const float2*)(s1);
    float2 f01 = *(const float2*)(s0 + 8);
    float2 f11 = *(const float2*)(s1 + 8);
    uint4 q;
    q.x = h2u(__floats2half2_rn(f00.x, f00.y));
    q.y = h2u(__floats2half2_rn(f10.x, f10.y));
    q.z = h2u(__floats2half2_rn(f01.x, f01.y));
    q.w = h2u(__floats2half2_rn(f11.x, f11.y));
    *(uint4*)((char*)o + (size_t)u * 16) = q;
}

// ---------------------------------------------------------------------------
// W fp32 [k][n] -> B-fragment fp16 layout.
// Unit u: lane=u&31, cb=(u>>5)&7, kk=(u>>8)&3, kch=(u>>10)&7, nblk=u>>13
//   n = nblk*128 + cb*16 + lane/4 ; k = kch*64 + kk*16 + (lane%4)*2
//   regs: b0(n,k) b1(n,k+8) b0(n+8,k) b1(n+8,k+8)
// ---------------------------------------------------------------------------
__global__ __launch_bounds__(256) void transW_frag_kernel(
    const float* __restrict__ W, __half* __restrict__ o)
{
    const int u = blockIdx.x * 256 + threadIdx.x;
    const int lane = u & 31, cb = (u >> 5) & 7, kk = (u >> 8) & 3;
    const int kch = (u >> 10) & 7, nblk = u >> 13;
    const int n = nblk * 128 + cb * 16 + (lane >> 2);
    const int k = kch * 64 + kk * 16 + (lane & 3) * 2;
    const float* s = W + (size_t)k * FD + n;
    uint4 q;
    q.x = h2u(__floats2half2_rn(s[0],          s[FD]));
    q.y = h2u(__floats2half2_rn(s[8 * FD],     s[9 * FD]));
    q.z = h2u(__floats2half2_rn(s[8],          s[FD + 8]));
    q.w = h2u(__floats2half2_rn(s[8 * FD + 8], s[9 * FD + 8]));
    *(uint4*)((char*)o + (size_t)u * 16) = q;
}

// ---------------------------------------------------------------------------
// out[row] = (prev ? prev[row] : 0) + b2[0]
// ---------------------------------------------------------------------------
__global__ __launch_bounds__(256) void init_out_kernel(
    const float* __restrict__ prev, const float* __restrict__ b2, float* __restrict__ out)
{
    const int i = blockIdx.x * 256 + threadIdx.x;
    out[i] = (prev ? prev[i] : 0.0f) + b2[0];
}

// ---------------------------------------------------------------------------
// fp16 mma.sync GEMM on fragment-layout operands, cp.async.bulk loads.
//  MODE 0:  H = relu(C + A2@Wtail + bias) -> outH (A-fragment layout)
//  MODE 1:  v = relu(C + A + bias); atomicAdd(dotOut, v@w2)
// ---------------------------------------------------------------------------
template <int MODE>
__global__ __launch_bounds__(256, 2) void gemm_mma_kernel(
    const __half* __restrict__ A,       // A-fragment layout
    const __half* __restrict__ B,       // B-fragment layout
    const float* __restrict__ bias,
    const float* __restrict__ A2, const int K2, const float* __restrict__ Wtail,
    __half* __restrict__ outH,
    const float* __restrict__ w2, float* __restrict__ dotOut)
{
    extern __shared__ __align__(128) char dsm[];
    __shared__ __align__(8) uint64_t s_mbar[NSTAGE];
    const uint32_t sbase = smem_u32(dsm);
    const uint32_t mb = smem_u32(s_mbar);

    const int tid = threadIdx.x;
    const int m0 = blockIdx.y * BM;
    const int n0 = blockIdx.x * BN;
    const int warp = tid >> 5, lane = tid & 31;
    const int warp_m = warp >> 2;          // 0..1 -> 64 rows
    const int warp_n = warp & 3;           // 0..3 -> 32 cols

    if (tid == 0) {
        #pragma unroll
        for (int s = 0; s < NSTAGE; s++) MB_INIT(mb + 8 * s, 1);
    }
    __syncthreads();

    const char* Asrc = (const char*)A + (size_t)blockIdx.y * MBLK_STRIDE;
    const char* Bsrc = (const char*)B + (size_t)blockIdx.x * MBLK_STRIDE;

    auto issue = [&](int ch) {
        const int s = ch % NSTAGE;
        const uint32_t st = sbase + s * STAGE_BYTES;
        MB_EXPECT(mb + 8 * s, STAGE_BYTES);
        bulk_cp(st,               Asrc + (size_t)ch * CHUNK_BYTES, CHUNK_BYTES, mb + 8 * s);
        bulk_cp(st + CHUNK_BYTES, Bsrc + (size_t)ch * CHUNK_BYTES, CHUNK_BYTES, mb + 8 * s);
    };

    if (tid == 0) { issue(0); issue(1); }

    // fragment LDS offsets (lane-consecutive 16B units; conflict-free)
    uint32_t aoff[4], boff[2];
    #pragma unroll
    for (int mt = 0; mt < 4; mt++)
        aoff[mt] = (uint32_t)(((warp_m * 4 + mt) * 32 + lane) * 16);
    #pragma unroll
    for (int pr = 0; pr < 2; pr++)
        boff[pr] = (uint32_t)(((warp_n * 2 + pr) * 32 + lane) * 16);

    float c[4][4][4];
    #pragma unroll
    for (int i = 0; i < 4; i++)
        #pragma unroll
        for (int j = 0; j < 4; j++)
            #pragma unroll
            for (int q = 0; q < 4; q++) c[i][j][q] = 0.0f;

    auto compute = [&](int s) {
        const uint32_t stA = sbase + s * STAGE_BYTES;
        const uint32_t stB = stA + CHUNK_BYTES;
        #pragma unroll
        for (int kk = 0; kk < 4; kk++) {
            const uint32_t ko = (uint32_t)(kk * 4096);
            uint32_t a[4][4], bf[4][2];
            #pragma unroll
            for (int mt = 0; mt < 4; mt++)
                LDS128(a[mt][0], a[mt][1], a[mt][2], a[mt][3], stA + ko + aoff[mt]);
            #pragma unroll
            for (int pr = 0; pr < 2; pr++) {
                uint32_t r0, r1, r2, r3;
                LDS128(r0, r1, r2, r3, stB + ko + boff[pr]);
                bf[2*pr][0] = r0; bf[2*pr][1] = r1;
                bf[2*pr+1][0] = r2; bf[2*pr+1][1] = r3;
            }
            #pragma unroll
            for (int mt = 0; mt < 4; mt++)
                #pragma unroll
                for (int nt = 0; nt < 4; nt++)
                    mma_f16(c[mt][nt], a[mt], bf[nt]);
        }
    };

    #pragma unroll 1
    for (int ch = 0; ch < FD / BK; ch++) {
        const int s = ch % NSTAGE;
        mb_wait_parity(mb + 8 * s, (ch / NSTAGE) & 1);
        __syncthreads();
        if (tid == 0 && ch + 2 < FD / BK) issue(ch + 2);
        compute(s);
    }

    // ---- epilogue ----
    const int qrow = lane >> 2;            // 0..7
    const int qcol = (lane & 3) * 2;       // 0,2,4,6
    // k-chunk of this warp's columns in the FULL 512-wide output:
    // col base = blockIdx.x*128 + warp_n*32  ->  kch = blockIdx.x*2 + warp_n/2
    const int kch_e = blockIdx.x * 2 + (warp_n >> 1);

    if (MODE == 0) {
        #pragma unroll
        for (int mt = 0; mt < 4; mt++) {
            const int rowA = m0 + warp_m * 64 + mt * 16 + qrow;
            const int rowB = rowA + 8;

            float a2A[12], a2B[12];
            for (int k = 0; k < K2; k++) {
                a2A[k] = __ldg(A2 + (size_t)rowA * K2 + k);
                a2B[k] = __ldg(A2 + (size_t)rowB * K2 + k);
            }

            float vA[4][2], vB[4][2];
            #pragma unroll
            for (int nt = 0; nt < 4; nt++) {
                const int colg = n0 + warp_n * 32 + nt * 8 + qcol;
                const float b0 = __ldg(bias + colg), b1 = __ldg(bias + colg + 1);
                float v0 = c[mt][nt][0] + b0, v1 = c[mt][nt][1] + b1;
                float v2 = c[mt][nt][2] + b0, v3 = c[mt][nt][3] + b1;
                for (int k = 0; k < K2; k++) {
                    const float w0 = __ldg(Wtail + (size_t)k * FD + colg);
                    const float w1 = __ldg(Wtail + (size_t)k * FD + colg + 1);
                    v0 += a2A[k] * w0; v1 += a2A[k] * w1;
                    v2 += a2B[k] * w0; v3 += a2B[k] * w1;
                }
                vA[nt][0] = fmaxf(v0, 0.0f); vA[nt][1] = fmaxf(v1, 0.0f);
                vB[nt][0] = fmaxf(v2, 0.0f); vB[nt][1] = fmaxf(v3, 0.0f);
            }
            // store in A-fragment layout (coalesced STG.128)
            #pragma unroll
            for (int np = 0; np < 2; np++) {
                const int kkx = (warp_n & 1) * 2 + np;
                const size_t off =
                    (((((size_t)blockIdx.y * 8 + kch_e) * 4 + kkx) * 8
                      + (warp_m * 4 + mt)) * 32 + lane) * 16;
                uint4 q;
                q.x = h2u(__floats2half2_rn(vA[2*np][0],   vA[2*np][1]));
                q.y = h2u(__floats2half2_rn(vB[2*np][0],   vB[2*np][1]));
                q.z = h2u(__floats2half2_rn(vA[2*np+1][0], vA[2*np+1][1]));
                q.w = h2u(__floats2half2_rn(vB[2*np+1][0], vB[2*np+1][1]));
                *(uint4*)((char*)outH + off) = q;
            }
        }
    } else {
        #pragma unroll
        for (int mt = 0; mt < 4; mt++) {
            const int rowA = m0 + warp_m * 64 + mt * 16 + qrow;
            const int rowB = rowA + 8;

            // residual from A (h in fragment layout): 2 LDG.128 per mt
            uint4 rf[2];
            #pragma unroll
            for (int np = 0; np < 2; np++) {
                const int kkx = (warp_n & 1) * 2 + np;
                const size_t off =
                    (((((size_t)blockIdx.y * 8 + kch_e) * 4 + kkx) * 8
                      + (warp_m * 4 + mt)) * 32 + lane) * 16;
                rf[np] = *(const uint4*)((const char*)A + off);
            }
            const uint32_t rw[4][2] = {
                {rf[0].x, rf[0].y}, {rf[0].z, rf[0].w},
                {rf[1].x, rf[1].y}, {rf[1].z, rf[1].w}};

            float sA = 0.0f, sB = 0.0f;
            #pragma unroll
            for (int nt = 0; nt < 4; nt++) {
                const int colg = n0 + warp_n * 32 + nt * 8 + qcol;
                const float b0 = __ldg(bias + colg), b1 = __ldg(bias + colg + 1);
                float2 hA = __half22float2(*(const __half2*)&rw[nt][0]);
                float2 hB = __half22float2(*(const __half2*)&rw[nt][1]);
                float v0 = c[mt][nt][0] + b0 + hA.x;
                float v1 = c[mt][nt][1] + b1 + hA.y;
                float v2 = c[mt][nt][2] + b0 + hB.x;
                float v3 = c[mt][nt][3] + b1 + hB.y;
                v0 = fmaxf(v0, 0.0f); v1 = fmaxf(v1, 0.0f);
                v2 = fmaxf(v2, 0.0f); v3 = fmaxf(v3, 0.0f);
                const float w0 = __ldg(w2 + colg), w1 = __ldg(w2 + colg + 1);
                sA += v0 * w0 + v1 * w1;
                sB += v2 * w0 + v3 * w1;
            }
            sA += __shfl_xor_sync(0xFFFFFFFFu, sA, 1);
            sA += __shfl_xor_sync(0xFFFFFFFFu, sA, 2);
            sB += __shfl_xor_sync(0xFFFFFFFFu, sB, 1);
            sB += __shfl_xor_sync(0xFFFFFFFFu, sB, 2);
            if ((lane & 3) == 0) {
                atomicAdd(dotOut + rowA, sA);
                atomicAdd(dotOut + rowB, sB);
            }
        }
    }
}

// ---------------------------------------------------------------------------
// Host orchestration
// ---------------------------------------------------------------------------
extern "C" void kernel_launch(void* const* d_in, const int* in_sizes, int n_in,
                              void* d_out, int out_size)
{
    const float* latent = (const float*)d_in[0];
    const float* rp     = (const float*)d_in[1];
    const float* w1[3] = {(const float*)d_in[2],  (const float*)d_in[8],  (const float*)d_in[14]};
    const float* b1[3] = {(const float*)d_in[3],  (const float*)d_in[9],  (const float*)d_in[15]};
    const float* wr[3] = {(const float*)d_in[4],  (const float*)d_in[10], (const float*)d_in[16]};
    const float* br[3] = {(const float*)d_in[5],  (const float*)d_in[11], (const float*)d_in[17]};
    const float* w2[3] = {(const float*)d_in[6],  (const float*)d_in[12], (const float*)d_in[18]};
    const float* b2[3] = {(const float*)d_in[7],  (const float*)d_in[13], (const float*)d_in[19]};

    float *feat, *std1, *std2;
    __half *lat, *h, *w1T, *wrT;
    cudaGetSymbolAddress((void**)&feat, g_feat);
    cudaGetSymbolAddress((void**)&lat,  g_lat);
    cudaGetSymbolAddress((void**)&h,    g_h);
    cudaGetSymbolAddress((void**)&std1, g_std1);
    cudaGetSymbolAddress((void**)&std2, g_std2);
    cudaGetSymbolAddress((void**)&w1T,  g_w1T);
    cudaGetSymbolAddress((void**)&wrT,  g_wrT);

    float* out = (float*)d_out;

    cudaFuncSetAttribute(gemm_mma_kernel<0>, cudaFuncAttributeMaxDynamicSharedMemorySize, SMEM_TOTAL);
    cudaFuncSetAttribute(gemm_mma_kernel<1>, cudaFuncAttributeMaxDynamicSharedMemorySize, SMEM_TOTAL);

    const dim3 ggrid(FD / BN, MROWS / BM);   // (4, 256)

    conv_frag_kernel<<<MROWS * FD / 8 / 256, 256>>>(latent, lat);
    knn_feat_kernel<<<dim3(NPTS / 256, BATCH), 256>>>(rp, feat);

    const float* stdprev[3] = {nullptr, std1, std2};
    const float* a2s[3]     = {feat, std1, std2};
    const int    k2s[3]     = {12, 1, 1};
    float*       stdout_[3] = {std1, std2, out};

    for (int s = 0; s < 3; s++) {
        transW_frag_kernel<<<FD * FD / 8 / 256, 256>>>(w1[s], w1T);
        gemm_mma_kernel<0><<<ggrid, 256, SMEM_TOTAL>>>(
            lat, w1T, b1[s],
            a2s[s], k2s[s], w1[s] + (size_t)FD * FD,
            h, nullptr, nullptr);
        transW_frag_kernel<<<FD * FD / 8 / 256, 256>>>(wr[s], wrT);
        init_out_kernel<<<MROWS / 256, 256>>>(stdprev[s], b2[s], stdout_[s]);
        gemm_mma_kernel<1><<<ggrid, 256, SMEM_TOTAL>>>(
            h, wrT, br[s],
            nullptr, 0, nullptr,
            nullptr, w2[s], stdout_[s]);
    }
}